// round 9
// baseline (speedup 1.0000x reference)
#include <cuda_runtime.h>
#include <cuda_bf16.h>
#include <stdint.h>

#define BATCH 8192
#define D_IN  1024
#define H1    2048
#define H2    2048
#define N_CLS 1000

// ---------------- scratch (device globals; no allocations allowed) ----------
__device__ float g_a1[(size_t)BATCH * H1];
__device__ float g_a2[(size_t)BATCH * H2];
__device__ __align__(256) __nv_bfloat16 g_xhi[(size_t)BATCH * D_IN];
__device__ __align__(256) __nv_bfloat16 g_xlo[(size_t)BATCH * D_IN];
__device__ __align__(256) __nv_bfloat16 g_a1hi[(size_t)BATCH * H1];
__device__ __align__(256) __nv_bfloat16 g_a1lo[(size_t)BATCH * H1];
__device__ __align__(256) __nv_bfloat16 g_a2hi[(size_t)BATCH * H2];
__device__ __align__(256) __nv_bfloat16 g_a2lo[(size_t)BATCH * H2];
__device__ __align__(256) __nv_bfloat16 g_w1hi[(size_t)H1 * D_IN];
__device__ __align__(256) __nv_bfloat16 g_w1lo[(size_t)H1 * D_IN];
__device__ __align__(256) __nv_bfloat16 g_w2hi[(size_t)H2 * H1];
__device__ __align__(256) __nv_bfloat16 g_w2lo[(size_t)H2 * H1];
__device__ __align__(256) __nv_bfloat16 g_w3hi[(size_t)N_CLS * H2];
__device__ __align__(256) __nv_bfloat16 g_w3lo[(size_t)N_CLS * H2];
__device__ __align__(256) __nv_bfloat16 g_xbT[(size_t)D_IN * BATCH];
__device__ __align__(256) __nv_bfloat16 g_a1bT[(size_t)H1 * BATCH];
__device__ __align__(256) __nv_bfloat16 g_a2bT[(size_t)H2 * BATCH];
__device__ __align__(256) __nv_bfloat16 g_lbT[(size_t)N_CLS * BATCH];

// ---------------- PTX helpers (sm_80-portable) ------------------------------
__device__ __forceinline__ uint32_t su32(const void* p) {
    uint32_t a;
    asm("{ .reg .u64 t; cvta.to.shared.u64 t, %1; cvt.u32.u64 %0, t; }" : "=r"(a) : "l"(p));
    return a;
}
__device__ __forceinline__ void ldsm4(uint32_t* r, uint32_t a) {
    asm volatile("ldmatrix.sync.aligned.m8n8.x4.shared.b16 {%0,%1,%2,%3}, [%4];"
                 : "=r"(r[0]), "=r"(r[1]), "=r"(r[2]), "=r"(r[3]) : "r"(a));
}
__device__ __forceinline__ void mma_bf(float* c, const uint32_t* a, const uint32_t* b) {
    asm volatile(
        "mma.sync.aligned.m16n8k16.row.col.f32.bf16.bf16.f32 "
        "{%0,%1,%2,%3}, {%4,%5,%6,%7}, {%8,%9}, {%0,%1,%2,%3};"
        : "+f"(c[0]), "+f"(c[1]), "+f"(c[2]), "+f"(c[3])
        : "r"(a[0]), "r"(a[1]), "r"(a[2]), "r"(a[3]), "r"(b[0]), "r"(b[1]));
}
__device__ __forceinline__ void cpa(uint32_t d, const void* s, int nbytes) {
    asm volatile("cp.async.cg.shared.global [%0], [%1], 16, %2;"
                 :: "r"(d), "l"(s), "r"(nbytes) : "memory");
}
#define CP_COMMIT() asm volatile("cp.async.commit_group;" ::: "memory")
#define CP_WAIT0()  asm volatile("cp.async.wait_group 0;" ::: "memory")
#define CP_WAIT1()  asm volatile("cp.async.wait_group 1;" ::: "memory")

// Conflict-free tile layout: logical rows x 4 chunks(16B) -> phys 128B rows,
// XOR swizzle kills ldmatrix bank conflicts. Valid for row < 256 (16KB region).
__device__ __forceinline__ uint32_t tadr(int row, int ch) {
    return (uint32_t)((row >> 1) * 128 +
                      (((((row & 1) << 2) | ch) ^ ((row >> 1) & 7)) << 4));
}
__device__ __forceinline__ uint32_t pk(__nv_bfloat16 a, __nv_bfloat16 b) {
    return (uint32_t)__bfloat16_as_ushort(a) | ((uint32_t)__bfloat16_as_ushort(b) << 16);
}

// ---------------- prepack: fp32 -> (hi, lo) bf16 ----------------------------
__global__ void split_k(const float* __restrict__ in, __nv_bfloat16* __restrict__ hi,
                        __nv_bfloat16* __restrict__ lo, size_t n4)
{
    size_t i = (size_t)blockIdx.x * blockDim.x + threadIdx.x;
    size_t stride = (size_t)gridDim.x * blockDim.x;
    for (; i < n4; i += stride) {
        float4 v = ((const float4*)in)[i];
        __nv_bfloat16 h0 = __float2bfloat16(v.x), h1 = __float2bfloat16(v.y);
        __nv_bfloat16 h2 = __float2bfloat16(v.z), h3 = __float2bfloat16(v.w);
        uint2 hp, lp;
        hp.x = pk(h0, h1); hp.y = pk(h2, h3);
        lp.x = pk(__float2bfloat16(v.x - __bfloat162float(h0)),
                  __float2bfloat16(v.y - __bfloat162float(h1)));
        lp.y = pk(__float2bfloat16(v.z - __bfloat162float(h2)),
                  __float2bfloat16(v.w - __bfloat162float(h3)));
        ((uint2*)hi)[i] = hp;
        ((uint2*)lo)[i] = lp;
    }
}

// ---------------- prepack: binarize + transpose to bf16 ----------------------
__global__ void binT_k(const float* __restrict__ in, __nv_bfloat16* __restrict__ out,
                       int R, int C)
{
    __shared__ float t[32][33];
    const int c0 = blockIdx.x * 32, r0 = blockIdx.y * 32;
    const int tx = threadIdx.x, ty = threadIdx.y;  // 32 x 8
#pragma unroll
    for (int i = 0; i < 4; i++) {
        int r = r0 + ty + i * 8, c = c0 + tx;
        t[ty + i * 8][tx] = (c < C) ? in[(size_t)r * C + c] : 0.f;
    }
    __syncthreads();
    const __nv_bfloat16 one = __float2bfloat16(1.f);
    const __nv_bfloat16 zero = __float2bfloat16(0.f);
#pragma unroll
    for (int i = 0; i < 4; i++) {
        int oc = c0 + ty + i * 8;
        if (oc < C)
            out[(size_t)oc * R + r0 + tx] = (t[tx][ty + i * 8] > 0.f) ? one : zero;
    }
}

// ---------------- GEMM engine: 128x256 CTA tile, 64x64 warp tile -------------
// C[M,N] = A @ B^T (+bias, relu). A [M,K], B [N,K] bf16 (hi/lo when SPLIT).
// MODE: 0 = plain (coact), 1 = split+bias+relu, 2 = split+bias
#define STAGES 3
// per-stage bytes: SPLIT: Ah 8K | Al 8K | Bh 16K | Bl 16K = 48K. MODE0: A 8K | B 16K = 24K.
template <int MODE>
__global__ void __launch_bounds__(256)
gemm_mma(const __nv_bfloat16* __restrict__ Ah, const __nv_bfloat16* __restrict__ Al,
         const __nv_bfloat16* __restrict__ Bh, const __nv_bfloat16* __restrict__ Bl,
         const float* __restrict__ bias, float* __restrict__ C,
         int M, int N, int K)
{
    constexpr bool SPLIT = (MODE != 0);
    constexpr int STG = SPLIT ? 49152 : 24576;
    constexpr int OFF_AL = 8192;
    constexpr int OFF_B  = SPLIT ? 16384 : 8192;
    constexpr int OFF_BL = 32768;
    extern __shared__ char smem[];
    const uint32_t sb = su32(smem);

    const int tid = threadIdx.x;
    const int lane = tid & 31, wid = tid >> 5;
    const int warp_m = wid & 1, warp_n = wid >> 1;     // 2 x 4 warps, 64x64 each
    const int m0 = blockIdx.y * 128, n0 = blockIdx.x * 256;

    float acc[4][8][4];
#pragma unroll
    for (int mi = 0; mi < 4; mi++)
#pragma unroll
        for (int ni = 0; ni < 8; ni++)
#pragma unroll
            for (int e = 0; e < 4; e++) acc[mi][ni][e] = 0.f;

    const int T = K >> 5;

    auto issue = [&](int t) {
        const uint32_t s = sb + (t % STAGES) * STG;
        const int k0 = t * 32;
        // A: 128 rows x 4 chunks = 512 ids
#pragma unroll
        for (int j = 0; j < 2; j++) {
            const int cid = j * 256 + tid;
            const int row = cid >> 2, ch = cid & 3;
            const uint32_t soff = tadr(row, ch);
            cpa(s + soff, Ah + (size_t)(m0 + row) * K + k0 + ch * 8, 16);
            if (SPLIT)
                cpa(s + OFF_AL + soff, Al + (size_t)(m0 + row) * K + k0 + ch * 8, 16);
        }
        // B: 256 rows x 4 chunks = 1024 ids
#pragma unroll
        for (int j = 0; j < 4; j++) {
            const int cid = j * 256 + tid;
            const int row = cid >> 2, ch = cid & 3;
            const uint32_t soff = tadr(row, ch);
            const int brow = n0 + row;
            const int ok = brow < N;
            cpa(s + OFF_B + soff, Bh + (size_t)(ok ? brow : 0) * K + k0 + ch * 8, ok ? 16 : 0);
            if (SPLIT)
                cpa(s + OFF_BL + soff, Bl + (size_t)(ok ? brow : 0) * K + k0 + ch * 8, ok ? 16 : 0);
        }
        CP_COMMIT();
    };

    issue(0);
    issue(1);

    for (int t = 0; t < T; t++) {
        if (t == T - 1) CP_WAIT0(); else CP_WAIT1();
        __syncthreads();
        if (t + 2 < T) issue(t + 2);

        const uint32_t s = sb + (t % STAGES) * STG;
        const uint32_t sA = s, sAl = s + OFF_AL;
        const uint32_t sB = s + OFF_B, sBl = s + OFF_BL;

#pragma unroll
        for (int ks = 0; ks < 2; ks++) {
            uint32_t ah[4][4], al_[4][4];
#pragma unroll
            for (int mi = 0; mi < 4; mi++) {
                const int row = warp_m * 64 + mi * 16 + (lane & 15);
                const int ch = ks * 2 + (lane >> 4);
                const uint32_t off = tadr(row, ch);
                ldsm4(ah[mi], sA + off);
                if (SPLIT) ldsm4(al_[mi], sAl + off);
            }
#pragma unroll
            for (int np = 0; np < 4; np++) {     // ni pairs via ldsm4
                uint32_t bh[4], bl_[4];
                const int row = warp_n * 64 + (np * 2 + (lane >> 4)) * 8 + (lane & 7);
                const int ch = ks * 2 + ((lane >> 3) & 1);
                const uint32_t off = tadr(row, ch);
                ldsm4(bh, sB + off);
                if (SPLIT) ldsm4(bl_, sBl + off);
#pragma unroll
                for (int mi = 0; mi < 4; mi++) {
                    mma_bf(acc[mi][np * 2], ah[mi], bh);
                    mma_bf(acc[mi][np * 2 + 1], ah[mi], bh + 2);
                    if (SPLIT) {
                        mma_bf(acc[mi][np * 2], ah[mi], bl_);
                        mma_bf(acc[mi][np * 2 + 1], ah[mi], bl_ + 2);
                        mma_bf(acc[mi][np * 2], al_[mi], bh);
                        mma_bf(acc[mi][np * 2 + 1], al_[mi], bh + 2);
                    }
                }
            }
        }
    }

    // epilogue
#pragma unroll
    for (int mi = 0; mi < 4; mi++) {
        const int r0 = m0 + warp_m * 64 + mi * 16 + (lane >> 2);
#pragma unroll
        for (int ni = 0; ni < 8; ni++) {
            const int col = n0 + warp_n * 64 + ni * 8 + (lane & 3) * 2;
            if (col < N) {
                float2 v0 = make_float2(acc[mi][ni][0], acc[mi][ni][1]);
                float2 v1 = make_float2(acc[mi][ni][2], acc[mi][ni][3]);
                if (SPLIT) {
                    const float b0 = __ldg(bias + col), b1 = __ldg(bias + col + 1);
                    v0.x += b0; v0.y += b1; v1.x += b0; v1.y += b1;
                    if (MODE == 1) {
                        v0.x = fmaxf(v0.x, 0.f); v0.y = fmaxf(v0.y, 0.f);
                        v1.x = fmaxf(v1.x, 0.f); v1.y = fmaxf(v1.y, 0.f);
                    }
                }
                *(float2*)(C + (size_t)r0 * N + col) = v0;
                *(float2*)(C + (size_t)(r0 + 8) * N + col) = v1;
            }
        }
    }
}

// ---------------- launch -----------------------------------------------------
extern "C" void kernel_launch(void* const* d_in, const int* in_sizes, int n_in,
                              void* d_out, int out_size)
{
    const float* x  = (const float*)d_in[0];
    const float* W1 = (const float*)d_in[1];
    const float* b1 = (const float*)d_in[2];
    const float* W2 = (const float*)d_in[3];
    const float* b2 = (const float*)d_in[4];
    const float* W3 = (const float*)d_in[5];
    const float* b3 = (const float*)d_in[6];

    float* out    = (float*)d_out;
    float* logits = out;
    float* coact0 = logits + (size_t)BATCH * N_CLS;
    float* coact1 = coact0 + (size_t)D_IN * H1;
    float* coact2 = coact1 + (size_t)H1 * H2;

    float *a1, *a2;
    __nv_bfloat16 *xhi, *xlo, *a1hi, *a1lo, *a2hi, *a2lo;
    __nv_bfloat16 *w1hi, *w1lo, *w2hi, *w2lo, *w3hi, *w3lo;
    __nv_bfloat16 *xbT, *a1bT, *a2bT, *lbT;
    cudaGetSymbolAddress((void**)&a1, g_a1);
    cudaGetSymbolAddress((void**)&a2, g_a2);
    cudaGetSymbolAddress((void**)&xhi, g_xhi);   cudaGetSymbolAddress((void**)&xlo, g_xlo);
    cudaGetSymbolAddress((void**)&a1hi, g_a1hi); cudaGetSymbolAddress((void**)&a1lo, g_a1lo);
    cudaGetSymbolAddress((void**)&a2hi, g_a2hi); cudaGetSymbolAddress((void**)&a2lo, g_a2lo);
    cudaGetSymbolAddress((void**)&w1hi, g_w1hi); cudaGetSymbolAddress((void**)&w1lo, g_w1lo);
    cudaGetSymbolAddress((void**)&w2hi, g_w2hi); cudaGetSymbolAddress((void**)&w2lo, g_w2lo);
    cudaGetSymbolAddress((void**)&w3hi, g_w3hi); cudaGetSymbolAddress((void**)&w3lo, g_w3lo);
    cudaGetSymbolAddress((void**)&xbT, g_xbT);   cudaGetSymbolAddress((void**)&a1bT, g_a1bT);
    cudaGetSymbolAddress((void**)&a2bT, g_a2bT); cudaGetSymbolAddress((void**)&lbT, g_lbT);

    static bool s_init = false;
    static cudaStream_t s_side;
    static cudaEvent_t evPrep1, evPrep2, evC0, evC1;
    if (!s_init) {
        cudaStreamCreateWithFlags(&s_side, cudaStreamNonBlocking);
        cudaEventCreateWithFlags(&evPrep1, cudaEventDisableTiming);
        cudaEventCreateWithFlags(&evPrep2, cudaEventDisableTiming);
        cudaEventCreateWithFlags(&evC0, cudaEventDisableTiming);
        cudaEventCreateWithFlags(&evC1, cudaEventDisableTiming);
        cudaFuncSetAttribute(gemm_mma<0>, cudaFuncAttributeMaxDynamicSharedMemorySize, 24576 * STAGES);
        cudaFuncSetAttribute(gemm_mma<1>, cudaFuncAttributeMaxDynamicSharedMemorySize, 49152 * STAGES);
        cudaFuncSetAttribute(gemm_mma<2>, cudaFuncAttributeMaxDynamicSharedMemorySize, 49152 * STAGES);
        s_init = true;
    }

    const dim3 blk(256);
    const dim3 tb(32, 8);
    const int SM0 = 24576 * STAGES, SM1 = 49152 * STAGES;

    // prepack inputs + weights (main stream)
    split_k<<<1024, 256>>>(x,  xhi,  xlo,  (size_t)BATCH * D_IN / 4);
    split_k<<<1024, 256>>>(W1, w1hi, w1lo, (size_t)H1 * D_IN / 4);
    split_k<<<1024, 256>>>(W2, w2hi, w2lo, (size_t)H2 * H1 / 4);
    split_k<<<1024, 256>>>(W3, w3hi, w3lo, (size_t)N_CLS * H2 / 4);
    binT_k<<<dim3(D_IN / 32, BATCH / 32), tb>>>(x, xbT, BATCH, D_IN);

    // fwd1: a1 = relu(x @ W1^T + b1)
    gemm_mma<1><<<dim3(H1 / 256, BATCH / 128), blk, SM1>>>(xhi, xlo, w1hi, w1lo, b1, a1, BATCH, H1, D_IN);
    split_k<<<1024, 256>>>(a1, a1hi, a1lo, (size_t)BATCH * H1 / 4);
    binT_k<<<dim3(H1 / 32, BATCH / 32), tb>>>(a1, a1bT, BATCH, H1);
    cudaEventRecord(evPrep1, 0);

    // side stream: coact0 overlaps fwd2
    cudaStreamWaitEvent(s_side, evPrep1, 0);
    gemm_mma<0><<<dim3(H1 / 256, D_IN / 128), blk, SM0, s_side>>>(
        xbT, nullptr, a1bT, nullptr, nullptr, coact0, D_IN, H1, BATCH);
    cudaEventRecord(evC0, s_side);

    // fwd2: a2 = relu(a1 @ W2^T + b2)
    gemm_mma<1><<<dim3(H2 / 256, BATCH / 128), blk, SM1>>>(a1hi, a1lo, w2hi, w2lo, b2, a2, BATCH, H2, H1);
    split_k<<<1024, 256>>>(a2, a2hi, a2lo, (size_t)BATCH * H2 / 4);
    binT_k<<<dim3(H2 / 32, BATCH / 32), tb>>>(a2, a2bT, BATCH, H2);
    cudaEventRecord(evPrep2, 0);

    // side stream: coact1 overlaps fwd3
    cudaStreamWaitEvent(s_side, evPrep2, 0);
    gemm_mma<0><<<dim3(H2 / 256, H1 / 128), blk, SM0, s_side>>>(
        a1bT, nullptr, a2bT, nullptr, nullptr, coact1, H1, H2, BATCH);
    cudaEventRecord(evC1, s_side);

    // fwd3: logits = a2 @ W3^T + b3
    gemm_mma<2><<<dim3((N_CLS + 255) / 256, BATCH / 128), blk, SM1>>>(
        a2hi, a2lo, w3hi, w3lo, b3, logits, BATCH, N_CLS, H2);
    binT_k<<<dim3((N_CLS + 31) / 32, BATCH / 32), tb>>>(logits, lbT, BATCH, N_CLS);

    // coact2 on main stream
    gemm_mma<0><<<dim3((N_CLS + 255) / 256, H2 / 128), blk, SM0>>>(
        a2bT, nullptr, lbT, nullptr, nullptr, coact2, H2, N_CLS, BATCH);

    // join side stream
    cudaStreamWaitEvent(0, evC0, 0);
    cudaStreamWaitEvent(0, evC1, 0);
}

// round 11
// speedup vs baseline: 1.1698x; 1.1698x over previous
#include <cuda_runtime.h>
#include <cuda_bf16.h>
#include <stdint.h>

#define BATCH 8192
#define D_IN  1024
#define H1    2048
#define H2    2048
#define N_CLS 1000

// ---------------- scratch (device globals; no allocations allowed) ----------
__device__ float g_a1[(size_t)BATCH * H1];
__device__ float g_a2[(size_t)BATCH * H2];
__device__ __align__(256) __nv_bfloat16 g_xhi[(size_t)BATCH * D_IN];
__device__ __align__(256) __nv_bfloat16 g_xlo[(size_t)BATCH * D_IN];
__device__ __align__(256) __nv_bfloat16 g_a1hi[(size_t)BATCH * H1];
__device__ __align__(256) __nv_bfloat16 g_a1lo[(size_t)BATCH * H1];
__device__ __align__(256) __nv_bfloat16 g_a2hi[(size_t)BATCH * H2];
__device__ __align__(256) __nv_bfloat16 g_a2lo[(size_t)BATCH * H2];
__device__ __align__(256) __nv_bfloat16 g_w1hi[(size_t)H1 * D_IN];
__device__ __align__(256) __nv_bfloat16 g_w1lo[(size_t)H1 * D_IN];
__device__ __align__(256) __nv_bfloat16 g_w2hi[(size_t)H2 * H1];
__device__ __align__(256) __nv_bfloat16 g_w2lo[(size_t)H2 * H1];
__device__ __align__(256) __nv_bfloat16 g_w3hi[(size_t)N_CLS * H2];
__device__ __align__(256) __nv_bfloat16 g_w3lo[(size_t)N_CLS * H2];
__device__ __align__(256) __nv_bfloat16 g_xbT[(size_t)D_IN * BATCH];
__device__ __align__(256) __nv_bfloat16 g_a1bT[(size_t)H1 * BATCH];
__device__ __align__(256) __nv_bfloat16 g_a2bT[(size_t)H2 * BATCH];
__device__ __align__(256) __nv_bfloat16 g_lbT[(size_t)N_CLS * BATCH];

// ---------------- PTX helpers (sm_80-portable) ------------------------------
__device__ __forceinline__ uint32_t su32(const void* p) {
    uint32_t a;
    asm("{ .reg .u64 t; cvta.to.shared.u64 t, %1; cvt.u32.u64 %0, t; }" : "=r"(a) : "l"(p));
    return a;
}
__device__ __forceinline__ void ldsm4(uint32_t* r, uint32_t a) {
    asm volatile("ldmatrix.sync.aligned.m8n8.x4.shared.b16 {%0,%1,%2,%3}, [%4];"
                 : "=r"(r[0]), "=r"(r[1]), "=r"(r[2]), "=r"(r[3]) : "r"(a));
}
__device__ __forceinline__ void ldsm2(uint32_t* r, uint32_t a) {
    asm volatile("ldmatrix.sync.aligned.m8n8.x2.shared.b16 {%0,%1}, [%2];"
                 : "=r"(r[0]), "=r"(r[1]) : "r"(a));
}
__device__ __forceinline__ void mma_bf(float* c, const uint32_t* a, const uint32_t* b) {
    asm volatile(
        "mma.sync.aligned.m16n8k16.row.col.f32.bf16.bf16.f32 "
        "{%0,%1,%2,%3}, {%4,%5,%6,%7}, {%8,%9}, {%0,%1,%2,%3};"
        : "+f"(c[0]), "+f"(c[1]), "+f"(c[2]), "+f"(c[3])
        : "r"(a[0]), "r"(a[1]), "r"(a[2]), "r"(a[3]), "r"(b[0]), "r"(b[1]));
}
__device__ __forceinline__ void cpa(uint32_t d, const void* s, int nbytes) {
    asm volatile("cp.async.cg.shared.global [%0], [%1], 16, %2;"
                 :: "r"(d), "l"(s), "r"(nbytes) : "memory");
}
#define CP_COMMIT() asm volatile("cp.async.commit_group;" ::: "memory")
#define CP_WAIT0()  asm volatile("cp.async.wait_group 0;" ::: "memory")
#define CP_WAIT1()  asm volatile("cp.async.wait_group 1;" ::: "memory")

// Conflict-free tile layout: logical 128 rows x 4 chunks(16B) -> 64 phys rows x 128B,
// XOR swizzle kills ldmatrix bank conflicts.
__device__ __forceinline__ uint32_t tadr(int row, int ch) {
    return (uint32_t)((row >> 1) * 128 +
                      (((((row & 1) << 2) | ch) ^ ((row >> 1) & 7)) << 4));
}
__device__ __forceinline__ uint32_t pk(__nv_bfloat16 a, __nv_bfloat16 b) {
    return (uint32_t)__bfloat16_as_ushort(a) | ((uint32_t)__bfloat16_as_ushort(b) << 16);
}

// ---------------- prepack: fp32 -> (hi, lo) bf16 ----------------------------
__global__ void split_k(const float* __restrict__ in, __nv_bfloat16* __restrict__ hi,
                        __nv_bfloat16* __restrict__ lo, size_t n4)
{
    size_t i = (size_t)blockIdx.x * blockDim.x + threadIdx.x;
    size_t stride = (size_t)gridDim.x * blockDim.x;
    for (; i < n4; i += stride) {
        float4 v = ((const float4*)in)[i];
        __nv_bfloat16 h0 = __float2bfloat16(v.x), h1 = __float2bfloat16(v.y);
        __nv_bfloat16 h2 = __float2bfloat16(v.z), h3 = __float2bfloat16(v.w);
        uint2 hp, lp;
        hp.x = pk(h0, h1); hp.y = pk(h2, h3);
        lp.x = pk(__float2bfloat16(v.x - __bfloat162float(h0)),
                  __float2bfloat16(v.y - __bfloat162float(h1)));
        lp.y = pk(__float2bfloat16(v.z - __bfloat162float(h2)),
                  __float2bfloat16(v.w - __bfloat162float(h3)));
        ((uint2*)hi)[i] = hp;
        ((uint2*)lo)[i] = lp;
    }
}

// ---------------- prepack: binarize + transpose to bf16 ----------------------
__global__ void binT_k(const float* __restrict__ in, __nv_bfloat16* __restrict__ out,
                       int R, int C)
{
    __shared__ float t[32][33];
    const int c0 = blockIdx.x * 32, r0 = blockIdx.y * 32;
    const int tx = threadIdx.x, ty = threadIdx.y;  // 32 x 8
#pragma unroll
    for (int i = 0; i < 4; i++) {
        int r = r0 + ty + i * 8, c = c0 + tx;
        t[ty + i * 8][tx] = (c < C) ? in[(size_t)r * C + c] : 0.f;
    }
    __syncthreads();
    const __nv_bfloat16 one = __float2bfloat16(1.f);
    const __nv_bfloat16 zero = __float2bfloat16(0.f);
#pragma unroll
    for (int i = 0; i < 4; i++) {
        int oc = c0 + ty + i * 8;
        if (oc < C)
            out[(size_t)oc * R + r0 + tx] = (t[tx][ty + i * 8] > 0.f) ? one : zero;
    }
}

// ---------------- fused postproc: read act once -> hi, lo, binT --------------
// in fp32 [R, C]; hi/lo bf16 [R, C]; bT bf16 [C, R] binarized. C % 32 == 0.
__global__ void post_k(const float* __restrict__ in, __nv_bfloat16* __restrict__ hi,
                       __nv_bfloat16* __restrict__ lo, __nv_bfloat16* __restrict__ bT,
                       int R, int C)
{
    __shared__ float t[32][33];
    const int c0 = blockIdx.x * 32, r0 = blockIdx.y * 32;
    const int tx = threadIdx.x, ty = threadIdx.y;  // 32 x 8
#pragma unroll
    for (int i = 0; i < 4; i++) {
        int r = r0 + ty + i * 8, c = c0 + tx;
        float v = in[(size_t)r * C + c];
        t[ty + i * 8][tx] = v;
        __nv_bfloat16 h = __float2bfloat16(v);
        hi[(size_t)r * C + c] = h;
        lo[(size_t)r * C + c] = __float2bfloat16(v - __bfloat162float(h));
    }
    __syncthreads();
    const __nv_bfloat16 one = __float2bfloat16(1.f);
    const __nv_bfloat16 zero = __float2bfloat16(0.f);
#pragma unroll
    for (int i = 0; i < 4; i++) {
        int oc = c0 + ty + i * 8;
        bT[(size_t)oc * R + r0 + tx] = (t[tx][ty + i * 8] > 0.f) ? one : zero;
    }
}

// ---------------- GEMM engine (R7-proven config) -----------------------------
// C[M,N] = A @ B^T (+bias, relu). A [M,K], B [N,K] bf16 (hi/lo when SPLIT).
// MODE: 0 = plain (coact), 1 = split+bias+relu, 2 = split+bias
#define STAGES 3
template <int MODE>
__global__ void __launch_bounds__(256)
gemm_mma(const __nv_bfloat16* __restrict__ Ah, const __nv_bfloat16* __restrict__ Al,
         const __nv_bfloat16* __restrict__ Bh, const __nv_bfloat16* __restrict__ Bl,
         const float* __restrict__ bias, float* __restrict__ C,
         int M, int N, int K)
{
    constexpr bool SPLIT = (MODE != 0);
    constexpr int NMAT = SPLIT ? 4 : 2;
    constexpr int STG = NMAT * 8192;
    extern __shared__ char smem[];
    const uint32_t sb = su32(smem);

    const int tid = threadIdx.x;
    const int lane = tid & 31, wid = tid >> 5;
    const int warp_m = wid & 1, warp_n = wid >> 1;     // 2 x 4 warp grid
    const int m0 = blockIdx.y * 128, n0 = blockIdx.x * 128;

    float acc[4][4][4];
#pragma unroll
    for (int mi = 0; mi < 4; mi++)
#pragma unroll
        for (int ni = 0; ni < 4; ni++)
#pragma unroll
            for (int e = 0; e < 4; e++) acc[mi][ni][e] = 0.f;

    const int T = K >> 5;

    auto issue = [&](int t) {
        const int buf = t % STAGES;
        const uint32_t s = sb + buf * STG;
        const int k0 = t * 32;
#pragma unroll
        for (int j = 0; j < 2; j++) {
            const int cid = j * 256 + tid;
            const int row = cid >> 2, ch = cid & 3;
            const uint32_t soff = tadr(row, ch);
            cpa(s + soff, Ah + (size_t)(m0 + row) * K + k0 + ch * 8, 16);
            if (SPLIT)
                cpa(s + 8192 + soff, Al + (size_t)(m0 + row) * K + k0 + ch * 8, 16);
            const int brow = n0 + row;
            const int ok = brow < N;
            const __nv_bfloat16* pb = Bh + (size_t)(ok ? brow : 0) * K + k0 + ch * 8;
            cpa(s + (SPLIT ? 2 : 1) * 8192 + soff, pb, ok ? 16 : 0);
            if (SPLIT) {
                const __nv_bfloat16* pbl = Bl + (size_t)(ok ? brow : 0) * K + k0 + ch * 8;
                cpa(s + 3 * 8192 + soff, pbl, ok ? 16 : 0);
            }
        }
        CP_COMMIT();
    };

    issue(0);
    issue(1);

    for (int t = 0; t < T; t++) {
        if (t == T - 1) CP_WAIT0(); else CP_WAIT1();
        __syncthreads();
        if (t + 2 < T) issue(t + 2);

        const uint32_t s = sb + (t % STAGES) * STG;
        const uint32_t sA = s, sAl = s + 8192;
        const uint32_t sB = s + (SPLIT ? 2 : 1) * 8192, sBl = s + 3 * 8192;

#pragma unroll
        for (int ks = 0; ks < 2; ks++) {
            uint32_t ah[4][4], al_[4][4], bh[4][2], bl_[4][2];
#pragma unroll
            for (int mi = 0; mi < 4; mi++) {
                const int row = warp_m * 64 + mi * 16 + (lane & 15);
                const int ch = ks * 2 + (lane >> 4);
                const uint32_t off = tadr(row, ch);
                ldsm4(ah[mi], sA + off);
                if (SPLIT) ldsm4(al_[mi], sAl + off);
            }
#pragma unroll
            for (int ni = 0; ni < 4; ni++) {
                const int row = warp_n * 32 + ni * 8 + (lane & 7);
                const int ch = ks * 2 + ((lane >> 3) & 1);
                const uint32_t off = tadr(row, ch);
                ldsm2(bh[ni], sB + off);
                if (SPLIT) ldsm2(bl_[ni], sBl + off);
            }
#pragma unroll
            for (int mi = 0; mi < 4; mi++)
#pragma unroll
                for (int ni = 0; ni < 4; ni++) {
                    mma_bf(acc[mi][ni], ah[mi], bh[ni]);
                    if (SPLIT) {
                        mma_bf(acc[mi][ni], ah[mi], bl_[ni]);
                        mma_bf(acc[mi][ni], al_[mi], bh[ni]);
                    }
                }
        }
    }

    // epilogue
#pragma unroll
    for (int mi = 0; mi < 4; mi++) {
        const int r0 = m0 + warp_m * 64 + mi * 16 + (lane >> 2);
#pragma unroll
        for (int ni = 0; ni < 4; ni++) {
            const int col = n0 + warp_n * 32 + ni * 8 + (lane & 3) * 2;
            if (col < N) {
                float2 v0 = make_float2(acc[mi][ni][0], acc[mi][ni][1]);
                float2 v1 = make_float2(acc[mi][ni][2], acc[mi][ni][3]);
                if (SPLIT) {
                    const float b0 = __ldg(bias + col), b1 = __ldg(bias + col + 1);
                    v0.x += b0; v0.y += b1; v1.x += b0; v1.y += b1;
                    if (MODE == 1) {
                        v0.x = fmaxf(v0.x, 0.f); v0.y = fmaxf(v0.y, 0.f);
                        v1.x = fmaxf(v1.x, 0.f); v1.y = fmaxf(v1.y, 0.f);
                    }
                }
                *(float2*)(C + (size_t)r0 * N + col) = v0;
                *(float2*)(C + (size_t)(r0 + 8) * N + col) = v1;
            }
        }
    }
}

// ---------------- launch -----------------------------------------------------
extern "C" void kernel_launch(void* const* d_in, const int* in_sizes, int n_in,
                              void* d_out, int out_size)
{
    const float* x  = (const float*)d_in[0];
    const float* W1 = (const float*)d_in[1];
    const float* b1 = (const float*)d_in[2];
    const float* W2 = (const float*)d_in[3];
    const float* b2 = (const float*)d_in[4];
    const float* W3 = (const float*)d_in[5];
    const float* b3 = (const float*)d_in[6];

    float* out    = (float*)d_out;
    float* logits = out;
    float* coact0 = logits + (size_t)BATCH * N_CLS;
    float* coact1 = coact0 + (size_t)D_IN * H1;
    float* coact2 = coact1 + (size_t)H1 * H2;

    float *a1, *a2;
    __nv_bfloat16 *xhi, *xlo, *a1hi, *a1lo, *a2hi, *a2lo;
    __nv_bfloat16 *w1hi, *w1lo, *w2hi, *w2lo, *w3hi, *w3lo;
    __nv_bfloat16 *xbT, *a1bT, *a2bT, *lbT;
    cudaGetSymbolAddress((void**)&a1, g_a1);
    cudaGetSymbolAddress((void**)&a2, g_a2);
    cudaGetSymbolAddress((void**)&xhi, g_xhi);   cudaGetSymbolAddress((void**)&xlo, g_xlo);
    cudaGetSymbolAddress((void**)&a1hi, g_a1hi); cudaGetSymbolAddress((void**)&a1lo, g_a1lo);
    cudaGetSymbolAddress((void**)&a2hi, g_a2hi); cudaGetSymbolAddress((void**)&a2lo, g_a2lo);
    cudaGetSymbolAddress((void**)&w1hi, g_w1hi); cudaGetSymbolAddress((void**)&w1lo, g_w1lo);
    cudaGetSymbolAddress((void**)&w2hi, g_w2hi); cudaGetSymbolAddress((void**)&w2lo, g_w2lo);
    cudaGetSymbolAddress((void**)&w3hi, g_w3hi); cudaGetSymbolAddress((void**)&w3lo, g_w3lo);
    cudaGetSymbolAddress((void**)&xbT, g_xbT);   cudaGetSymbolAddress((void**)&a1bT, g_a1bT);
    cudaGetSymbolAddress((void**)&a2bT, g_a2bT); cudaGetSymbolAddress((void**)&lbT, g_lbT);

    static bool s_init = false;
    static cudaStream_t s_side;
    static cudaEvent_t evFork, evW23, evPrep1, evPrep2, evC0, evC1;
    if (!s_init) {
        cudaStreamCreateWithFlags(&s_side, cudaStreamNonBlocking);
        cudaEventCreateWithFlags(&evFork, cudaEventDisableTiming);
        cudaEventCreateWithFlags(&evW23, cudaEventDisableTiming);
        cudaEventCreateWithFlags(&evPrep1, cudaEventDisableTiming);
        cudaEventCreateWithFlags(&evPrep2, cudaEventDisableTiming);
        cudaEventCreateWithFlags(&evC0, cudaEventDisableTiming);
        cudaEventCreateWithFlags(&evC1, cudaEventDisableTiming);
        cudaFuncSetAttribute(gemm_mma<0>, cudaFuncAttributeMaxDynamicSharedMemorySize, 2 * 8192 * STAGES);
        cudaFuncSetAttribute(gemm_mma<1>, cudaFuncAttributeMaxDynamicSharedMemorySize, 4 * 8192 * STAGES);
        cudaFuncSetAttribute(gemm_mma<2>, cudaFuncAttributeMaxDynamicSharedMemorySize, 4 * 8192 * STAGES);
        s_init = true;
    }

    const dim3 blk(256);
    const dim3 tb(32, 8);
    const int SM0 = 2 * 8192 * STAGES, SM1 = 4 * 8192 * STAGES;

    // capture-legal fork: side stream's FIRST op waits on an event from stream 0
    cudaEventRecord(evFork, 0);
    cudaStreamWaitEvent(s_side, evFork, 0);

    // main stream: prepack needed for fwd1
    split_k<<<1024, 256>>>(x,  xhi,  xlo,  (size_t)BATCH * D_IN / 4);
    split_k<<<1024, 256>>>(W1, w1hi, w1lo, (size_t)H1 * D_IN / 4);

    // side stream: W2/W3 split + binT(x), overlapping fwd1
    split_k<<<1024, 256, 0, s_side>>>(W2, w2hi, w2lo, (size_t)H2 * H1 / 4);
    split_k<<<1024, 256, 0, s_side>>>(W3, w3hi, w3lo, (size_t)N_CLS * H2 / 4);
    binT_k<<<dim3(D_IN / 32, BATCH / 32), tb, 0, s_side>>>(x, xbT, BATCH, D_IN);
    cudaEventRecord(evW23, s_side);

    // fwd1: a1 = relu(x @ W1^T + b1), fused postproc
    gemm_mma<1><<<dim3(H1 / 128, BATCH / 128), blk, SM1>>>(xhi, xlo, w1hi, w1lo, b1, a1, BATCH, H1, D_IN);
    post_k<<<dim3(H1 / 32, BATCH / 32), tb>>>(a1, a1hi, a1lo, a1bT, BATCH, H1);
    cudaEventRecord(evPrep1, 0);

    // side stream: coact0 overlaps fwd2
    cudaStreamWaitEvent(s_side, evPrep1, 0);
    gemm_mma<0><<<dim3(H1 / 128, D_IN / 128), blk, SM0, s_side>>>(
        xbT, nullptr, a1bT, nullptr, nullptr, coact0, D_IN, H1, BATCH);
    cudaEventRecord(evC0, s_side);

    // fwd2: a2 = relu(a1 @ W2^T + b2)  (needs w2 from side stream)
    cudaStreamWaitEvent(0, evW23, 0);
    gemm_mma<1><<<dim3(H2 / 128, BATCH / 128), blk, SM1>>>(a1hi, a1lo, w2hi, w2lo, b2, a2, BATCH, H2, H1);
    post_k<<<dim3(H2 / 32, BATCH / 32), tb>>>(a2, a2hi, a2lo, a2bT, BATCH, H2);
    cudaEventRecord(evPrep2, 0);

    // side stream: coact1 overlaps fwd3
    cudaStreamWaitEvent(s_side, evPrep2, 0);
    gemm_mma<0><<<dim3(H2 / 128, H1 / 128), blk, SM0, s_side>>>(
        a1bT, nullptr, a2bT, nullptr, nullptr, coact1, H1, H2, BATCH);
    cudaEventRecord(evC1, s_side);

    // fwd3: logits = a2 @ W3^T + b3
    gemm_mma<2><<<dim3((N_CLS + 127) / 128, BATCH / 128), blk, SM1>>>(
        a2hi, a2lo, w3hi, w3lo, b3, logits, BATCH, N_CLS, H2);
    binT_k<<<dim3((N_CLS + 31) / 32, BATCH / 32), tb>>>(logits, lbT, BATCH, N_CLS);

    // coact2 on main stream
    gemm_mma<0><<<dim3((N_CLS + 127) / 128, H2 / 128), blk, SM0>>>(
        a2bT, nullptr, lbT, nullptr, nullptr, coact2, H2, N_CLS, BATCH);

    // join side stream
    cudaStreamWaitEvent(0, evC0, 0);
    cudaStreamWaitEvent(0, evC1, 0);
}

// round 12
// speedup vs baseline: 1.5166x; 1.2964x over previous
#include <cuda_runtime.h>
#include <cuda_bf16.h>
#include <cuda_fp16.h>
#include <stdint.h>

#define BATCH 8192
#define D_IN  1024
#define H1    2048
#define H2    2048
#define N_CLS 1000

// ---------------- scratch (device globals; no allocations allowed) ----------
__device__ float g_a1[(size_t)BATCH * H1];
__device__ float g_a2[(size_t)BATCH * H2];
__device__ __align__(256) __half g_xhi[(size_t)BATCH * D_IN];
__device__ __align__(256) __half g_xlo[(size_t)BATCH * D_IN];
__device__ __align__(256) __half g_a1hi[(size_t)BATCH * H1];
__device__ __align__(256) __half g_a1lo[(size_t)BATCH * H1];
__device__ __align__(256) __half g_a2hi[(size_t)BATCH * H2];
__device__ __align__(256) __half g_a2lo[(size_t)BATCH * H2];
__device__ __align__(256) __half g_w1h[(size_t)H1 * D_IN];
__device__ __align__(256) __half g_w2h[(size_t)H2 * H1];
__device__ __align__(256) __half g_w3h[(size_t)N_CLS * H2];
__device__ __align__(256) __nv_bfloat16 g_xbT[(size_t)D_IN * BATCH];
__device__ __align__(256) __nv_bfloat16 g_a1bT[(size_t)H1 * BATCH];
__device__ __align__(256) __nv_bfloat16 g_a2bT[(size_t)H2 * BATCH];
__device__ __align__(256) __nv_bfloat16 g_lbT[(size_t)N_CLS * BATCH];

// ---------------- PTX helpers (sm_80-portable) ------------------------------
__device__ __forceinline__ uint32_t su32(const void* p) {
    uint32_t a;
    asm("{ .reg .u64 t; cvta.to.shared.u64 t, %1; cvt.u32.u64 %0, t; }" : "=r"(a) : "l"(p));
    return a;
}
__device__ __forceinline__ void ldsm4(uint32_t* r, uint32_t a) {
    asm volatile("ldmatrix.sync.aligned.m8n8.x4.shared.b16 {%0,%1,%2,%3}, [%4];"
                 : "=r"(r[0]), "=r"(r[1]), "=r"(r[2]), "=r"(r[3]) : "r"(a));
}
__device__ __forceinline__ void ldsm2(uint32_t* r, uint32_t a) {
    asm volatile("ldmatrix.sync.aligned.m8n8.x2.shared.b16 {%0,%1}, [%2];"
                 : "=r"(r[0]), "=r"(r[1]) : "r"(a));
}
__device__ __forceinline__ void mma_bf(float* c, const uint32_t* a, const uint32_t* b) {
    asm volatile(
        "mma.sync.aligned.m16n8k16.row.col.f32.bf16.bf16.f32 "
        "{%0,%1,%2,%3}, {%4,%5,%6,%7}, {%8,%9}, {%0,%1,%2,%3};"
        : "+f"(c[0]), "+f"(c[1]), "+f"(c[2]), "+f"(c[3])
        : "r"(a[0]), "r"(a[1]), "r"(a[2]), "r"(a[3]), "r"(b[0]), "r"(b[1]));
}
__device__ __forceinline__ void mma_f16(float* c, const uint32_t* a, const uint32_t* b) {
    asm volatile(
        "mma.sync.aligned.m16n8k16.row.col.f32.f16.f16.f32 "
        "{%0,%1,%2,%3}, {%4,%5,%6,%7}, {%8,%9}, {%0,%1,%2,%3};"
        : "+f"(c[0]), "+f"(c[1]), "+f"(c[2]), "+f"(c[3])
        : "r"(a[0]), "r"(a[1]), "r"(a[2]), "r"(a[3]), "r"(b[0]), "r"(b[1]));
}
__device__ __forceinline__ void cpa(uint32_t d, const void* s, int nbytes) {
    asm volatile("cp.async.cg.shared.global [%0], [%1], 16, %2;"
                 :: "r"(d), "l"(s), "r"(nbytes) : "memory");
}
#define CP_COMMIT() asm volatile("cp.async.commit_group;" ::: "memory")
#define CP_WAIT0()  asm volatile("cp.async.wait_group 0;" ::: "memory")
#define CP_WAIT1()  asm volatile("cp.async.wait_group 1;" ::: "memory")

// Conflict-free tile layout: logical 128 rows x 4 chunks(16B) -> 64 phys rows x 128B,
// XOR swizzle kills ldmatrix bank conflicts.
__device__ __forceinline__ uint32_t tadr(int row, int ch) {
    return (uint32_t)((row >> 1) * 128 +
                      (((((row & 1) << 2) | ch) ^ ((row >> 1) & 7)) << 4));
}
__device__ __forceinline__ uint32_t pkh(__half a, __half b) {
    return (uint32_t)__half_as_ushort(a) | ((uint32_t)__half_as_ushort(b) << 16);
}

// ---------------- prepack: fp32 -> fp16 (weights) ----------------------------
__global__ void w16_k(const float* __restrict__ in, __half* __restrict__ out, size_t n4)
{
    size_t i = (size_t)blockIdx.x * blockDim.x + threadIdx.x;
    size_t stride = (size_t)gridDim.x * blockDim.x;
    for (; i < n4; i += stride) {
        float4 v = ((const float4*)in)[i];
        uint2 o;
        o.x = pkh(__float2half(v.x), __float2half(v.y));
        o.y = pkh(__float2half(v.z), __float2half(v.w));
        ((uint2*)out)[i] = o;
    }
}

// ---------------- fused postproc: read once -> fp16 hi, fp16 lo, bf16 binT ---
// in fp32 [R, C]; hi/lo fp16 [R, C]; bT bf16 [C, R] binarized. C % 32 == 0.
__global__ void post_k(const float* __restrict__ in, __half* __restrict__ hi,
                       __half* __restrict__ lo, __nv_bfloat16* __restrict__ bT,
                       int R, int C)
{
    __shared__ float t[32][33];
    const int c0 = blockIdx.x * 32, r0 = blockIdx.y * 32;
    const int tx = threadIdx.x, ty = threadIdx.y;  // 32 x 8
#pragma unroll
    for (int i = 0; i < 4; i++) {
        int r = r0 + ty + i * 8, c = c0 + tx;
        float v = in[(size_t)r * C + c];
        t[ty + i * 8][tx] = v;
        __half h = __float2half(v);
        hi[(size_t)r * C + c] = h;
        lo[(size_t)r * C + c] = __float2half(v - __half2float(h));
    }
    __syncthreads();
    const __nv_bfloat16 one = __float2bfloat16(1.f);
    const __nv_bfloat16 zero = __float2bfloat16(0.f);
#pragma unroll
    for (int i = 0; i < 4; i++) {
        int oc = c0 + ty + i * 8;
        bT[(size_t)oc * R + r0 + tx] = (t[tx][ty + i * 8] > 0.f) ? one : zero;
    }
}

// ---------------- binarize + transpose (logits only; ragged C) ---------------
__global__ void binT_k(const float* __restrict__ in, __nv_bfloat16* __restrict__ out,
                       int R, int C)
{
    __shared__ float t[32][33];
    const int c0 = blockIdx.x * 32, r0 = blockIdx.y * 32;
    const int tx = threadIdx.x, ty = threadIdx.y;  // 32 x 8
#pragma unroll
    for (int i = 0; i < 4; i++) {
        int r = r0 + ty + i * 8, c = c0 + tx;
        t[ty + i * 8][tx] = (c < C) ? in[(size_t)r * C + c] : 0.f;
    }
    __syncthreads();
    const __nv_bfloat16 one = __float2bfloat16(1.f);
    const __nv_bfloat16 zero = __float2bfloat16(0.f);
#pragma unroll
    for (int i = 0; i < 4; i++) {
        int oc = c0 + ty + i * 8;
        if (oc < C)
            out[(size_t)oc * R + r0 + tx] = (t[tx][ty + i * 8] > 0.f) ? one : zero;
    }
}

// ---------------- forward GEMM: fp16, A split (hi+lo), B single --------------
// C[M,N] = (Ahi+Alo) @ B^T + bias [+relu]. A [M,K] fp16 x2, B [N,K] fp16.
#define STAGES 3
#define FWD_STG 24576                 // Ah 8K | Al 8K | B 8K
#define FWD_SMEM (FWD_STG * STAGES)   // 72 KB -> 3 CTAs/SM
template <bool RELU>
__global__ void __launch_bounds__(256)
gemm_fwd(const __half* __restrict__ Ah, const __half* __restrict__ Al,
         const __half* __restrict__ B, const float* __restrict__ bias,
         float* __restrict__ C, int M, int N, int K)
{
    extern __shared__ char smem[];
    const uint32_t sb = su32(smem);

    const int tid = threadIdx.x;
    const int lane = tid & 31, wid = tid >> 5;
    const int warp_m = wid & 1, warp_n = wid >> 1;     // 2 x 4 warps
    const int m0 = blockIdx.y * 128, n0 = blockIdx.x * 128;

    float acc[4][4][4];
#pragma unroll
    for (int mi = 0; mi < 4; mi++)
#pragma unroll
        for (int ni = 0; ni < 4; ni++)
#pragma unroll
            for (int e = 0; e < 4; e++) acc[mi][ni][e] = 0.f;

    const int T = K >> 5;

    auto issue = [&](int t) {
        const uint32_t s = sb + (t % STAGES) * FWD_STG;
        const int k0 = t * 32;
#pragma unroll
        for (int j = 0; j < 2; j++) {
            const int cid = j * 256 + tid;
            const int row = cid >> 2, ch = cid & 3;
            const uint32_t soff = tadr(row, ch);
            cpa(s + soff, Ah + (size_t)(m0 + row) * K + k0 + ch * 8, 16);
            cpa(s + 8192 + soff, Al + (size_t)(m0 + row) * K + k0 + ch * 8, 16);
            const int brow = n0 + row;
            const int ok = brow < N;
            cpa(s + 16384 + soff, B + (size_t)(ok ? brow : 0) * K + k0 + ch * 8, ok ? 16 : 0);
        }
        CP_COMMIT();
    };

    issue(0);
    issue(1);

    for (int t = 0; t < T; t++) {
        if (t == T - 1) CP_WAIT0(); else CP_WAIT1();
        __syncthreads();
        if (t + 2 < T) issue(t + 2);

        const uint32_t s = sb + (t % STAGES) * FWD_STG;
        const uint32_t sA = s, sAl = s + 8192, sB = s + 16384;

#pragma unroll
        for (int ks = 0; ks < 2; ks++) {
            uint32_t ah[4][4], al_[4][4], bq[4][2];
#pragma unroll
            for (int mi = 0; mi < 4; mi++) {
                const int row = warp_m * 64 + mi * 16 + (lane & 15);
                const int ch = ks * 2 + (lane >> 4);
                const uint32_t off = tadr(row, ch);
                ldsm4(ah[mi], sA + off);
                ldsm4(al_[mi], sAl + off);
            }
#pragma unroll
            for (int ni = 0; ni < 4; ni++) {
                const int row = warp_n * 32 + ni * 8 + (lane & 7);
                const int ch = ks * 2 + ((lane >> 3) & 1);
                ldsm2(bq[ni], sB + tadr(row, ch));
            }
#pragma unroll
            for (int mi = 0; mi < 4; mi++)
#pragma unroll
                for (int ni = 0; ni < 4; ni++) {
                    mma_f16(acc[mi][ni], ah[mi], bq[ni]);
                    mma_f16(acc[mi][ni], al_[mi], bq[ni]);
                }
        }
    }

    // epilogue: bias (+relu), fp32 out
#pragma unroll
    for (int mi = 0; mi < 4; mi++) {
        const int r0 = m0 + warp_m * 64 + mi * 16 + (lane >> 2);
#pragma unroll
        for (int ni = 0; ni < 4; ni++) {
            const int col = n0 + warp_n * 32 + ni * 8 + (lane & 3) * 2;
            if (col < N) {
                const float b0 = __ldg(bias + col), b1 = __ldg(bias + col + 1);
                float2 v0 = make_float2(acc[mi][ni][0] + b0, acc[mi][ni][1] + b1);
                float2 v1 = make_float2(acc[mi][ni][2] + b0, acc[mi][ni][3] + b1);
                if (RELU) {
                    v0.x = fmaxf(v0.x, 0.f); v0.y = fmaxf(v0.y, 0.f);
                    v1.x = fmaxf(v1.x, 0.f); v1.y = fmaxf(v1.y, 0.f);
                }
                *(float2*)(C + (size_t)r0 * N + col) = v0;
                *(float2*)(C + (size_t)(r0 + 8) * N + col) = v1;
            }
        }
    }
}

// ---------------- coact GEMM: bf16 0/1, exact (R7-proven) --------------------
#define CO_STG 16384                  // A 8K | B 8K
#define CO_SMEM (CO_STG * STAGES)
__global__ void __launch_bounds__(256)
gemm_co(const __nv_bfloat16* __restrict__ A, const __nv_bfloat16* __restrict__ B,
        float* __restrict__ C, int M, int N, int K)
{
    extern __shared__ char smem[];
    const uint32_t sb = su32(smem);

    const int tid = threadIdx.x;
    const int lane = tid & 31, wid = tid >> 5;
    const int warp_m = wid & 1, warp_n = wid >> 1;
    const int m0 = blockIdx.y * 128, n0 = blockIdx.x * 128;

    float acc[4][4][4];
#pragma unroll
    for (int mi = 0; mi < 4; mi++)
#pragma unroll
        for (int ni = 0; ni < 4; ni++)
#pragma unroll
            for (int e = 0; e < 4; e++) acc[mi][ni][e] = 0.f;

    const int T = K >> 5;

    auto issue = [&](int t) {
        const uint32_t s = sb + (t % STAGES) * CO_STG;
        const int k0 = t * 32;
#pragma unroll
        for (int j = 0; j < 2; j++) {
            const int cid = j * 256 + tid;
            const int row = cid >> 2, ch = cid & 3;
            const uint32_t soff = tadr(row, ch);
            cpa(s + soff, A + (size_t)(m0 + row) * K + k0 + ch * 8, 16);
            const int brow = n0 + row;
            const int ok = brow < N;
            cpa(s + 8192 + soff, B + (size_t)(ok ? brow : 0) * K + k0 + ch * 8, ok ? 16 : 0);
        }
        CP_COMMIT();
    };

    issue(0);
    issue(1);

    for (int t = 0; t < T; t++) {
        if (t == T - 1) CP_WAIT0(); else CP_WAIT1();
        __syncthreads();
        if (t + 2 < T) issue(t + 2);

        const uint32_t s = sb + (t % STAGES) * CO_STG;
        const uint32_t sA = s, sB = s + 8192;

#pragma unroll
        for (int ks = 0; ks < 2; ks++) {
            uint32_t a[4][4], bq[4][2];
#pragma unroll
            for (int mi = 0; mi < 4; mi++) {
                const int row = warp_m * 64 + mi * 16 + (lane & 15);
                const int ch = ks * 2 + (lane >> 4);
                ldsm4(a[mi], sA + tadr(row, ch));
            }
#pragma unroll
            for (int ni = 0; ni < 4; ni++) {
                const int row = warp_n * 32 + ni * 8 + (lane & 7);
                const int ch = ks * 2 + ((lane >> 3) & 1);
                ldsm2(bq[ni], sB + tadr(row, ch));
            }
#pragma unroll
            for (int mi = 0; mi < 4; mi++)
#pragma unroll
                for (int ni = 0; ni < 4; ni++)
                    mma_bf(acc[mi][ni], a[mi], bq[ni]);
        }
    }

#pragma unroll
    for (int mi = 0; mi < 4; mi++) {
        const int r0 = m0 + warp_m * 64 + mi * 16 + (lane >> 2);
#pragma unroll
        for (int ni = 0; ni < 4; ni++) {
            const int col = n0 + warp_n * 32 + ni * 8 + (lane & 3) * 2;
            if (col < N) {
                *(float2*)(C + (size_t)r0 * N + col) =
                    make_float2(acc[mi][ni][0], acc[mi][ni][1]);
                *(float2*)(C + (size_t)(r0 + 8) * N + col) =
                    make_float2(acc[mi][ni][2], acc[mi][ni][3]);
            }
        }
    }
}

// ---------------- launch -----------------------------------------------------
extern "C" void kernel_launch(void* const* d_in, const int* in_sizes, int n_in,
                              void* d_out, int out_size)
{
    const float* x  = (const float*)d_in[0];
    const float* W1 = (const float*)d_in[1];
    const float* b1 = (const float*)d_in[2];
    const float* W2 = (const float*)d_in[3];
    const float* b2 = (const float*)d_in[4];
    const float* W3 = (const float*)d_in[5];
    const float* b3 = (const float*)d_in[6];

    float* out    = (float*)d_out;
    float* logits = out;
    float* coact0 = logits + (size_t)BATCH * N_CLS;
    float* coact1 = coact0 + (size_t)D_IN * H1;
    float* coact2 = coact1 + (size_t)H1 * H2;

    float *a1, *a2;
    __half *xhi, *xlo, *a1hi, *a1lo, *a2hi, *a2lo, *w1h, *w2h, *w3h;
    __nv_bfloat16 *xbT, *a1bT, *a2bT, *lbT;
    cudaGetSymbolAddress((void**)&a1, g_a1);
    cudaGetSymbolAddress((void**)&a2, g_a2);
    cudaGetSymbolAddress((void**)&xhi, g_xhi);   cudaGetSymbolAddress((void**)&xlo, g_xlo);
    cudaGetSymbolAddress((void**)&a1hi, g_a1hi); cudaGetSymbolAddress((void**)&a1lo, g_a1lo);
    cudaGetSymbolAddress((void**)&a2hi, g_a2hi); cudaGetSymbolAddress((void**)&a2lo, g_a2lo);
    cudaGetSymbolAddress((void**)&w1h, g_w1h);
    cudaGetSymbolAddress((void**)&w2h, g_w2h);
    cudaGetSymbolAddress((void**)&w3h, g_w3h);
    cudaGetSymbolAddress((void**)&xbT, g_xbT);   cudaGetSymbolAddress((void**)&a1bT, g_a1bT);
    cudaGetSymbolAddress((void**)&a2bT, g_a2bT); cudaGetSymbolAddress((void**)&lbT, g_lbT);

    static bool s_init = false;
    static cudaStream_t s_side;
    static cudaEvent_t evFork, evW23, evPrep1, evPrep2, evC0, evC1;
    if (!s_init) {
        cudaStreamCreateWithFlags(&s_side, cudaStreamNonBlocking);
        cudaEventCreateWithFlags(&evFork, cudaEventDisableTiming);
        cudaEventCreateWithFlags(&evW23, cudaEventDisableTiming);
        cudaEventCreateWithFlags(&evPrep1, cudaEventDisableTiming);
        cudaEventCreateWithFlags(&evPrep2, cudaEventDisableTiming);
        cudaEventCreateWithFlags(&evC0, cudaEventDisableTiming);
        cudaEventCreateWithFlags(&evC1, cudaEventDisableTiming);
        cudaFuncSetAttribute(gemm_fwd<true>, cudaFuncAttributeMaxDynamicSharedMemorySize, FWD_SMEM);
        cudaFuncSetAttribute(gemm_fwd<false>, cudaFuncAttributeMaxDynamicSharedMemorySize, FWD_SMEM);
        cudaFuncSetAttribute(gemm_co, cudaFuncAttributeMaxDynamicSharedMemorySize, CO_SMEM);
        s_init = true;
    }

    const dim3 blk(256);
    const dim3 tb(32, 8);

    // capture-legal fork: side stream's FIRST op waits on an event from stream 0
    cudaEventRecord(evFork, 0);
    cudaStreamWaitEvent(s_side, evFork, 0);

    // main stream: prepack needed for fwd1 (x hi/lo + xbT in one pass, W1 fp16)
    post_k<<<dim3(D_IN / 32, BATCH / 32), tb>>>(x, xhi, xlo, xbT, BATCH, D_IN);
    w16_k<<<1024, 256>>>(W1, w1h, (size_t)H1 * D_IN / 4);

    // side stream: W2/W3 fp16, overlapping fwd1
    w16_k<<<1024, 256, 0, s_side>>>(W2, w2h, (size_t)H2 * H1 / 4);
    w16_k<<<1024, 256, 0, s_side>>>(W3, w3h, (size_t)N_CLS * H2 / 4);
    cudaEventRecord(evW23, s_side);

    // fwd1: a1 = relu(x @ W1^T + b1), fused postproc
    gemm_fwd<true><<<dim3(H1 / 128, BATCH / 128), blk, FWD_SMEM>>>(
        xhi, xlo, w1h, b1, a1, BATCH, H1, D_IN);
    post_k<<<dim3(H1 / 32, BATCH / 32), tb>>>(a1, a1hi, a1lo, a1bT, BATCH, H1);
    cudaEventRecord(evPrep1, 0);

    // side stream: coact0 overlaps fwd2
    cudaStreamWaitEvent(s_side, evPrep1, 0);
    gemm_co<<<dim3(H1 / 128, D_IN / 128), blk, CO_SMEM, s_side>>>(
        xbT, a1bT, coact0, D_IN, H1, BATCH);
    cudaEventRecord(evC0, s_side);

    // fwd2: a2 = relu(a1 @ W2^T + b2)  (needs w2 from side stream)
    cudaStreamWaitEvent(0, evW23, 0);
    gemm_fwd<true><<<dim3(H2 / 128, BATCH / 128), blk, FWD_SMEM>>>(
        a1hi, a1lo, w2h, b2, a2, BATCH, H2, H1);
    post_k<<<dim3(H2 / 32, BATCH / 32), tb>>>(a2, a2hi, a2lo, a2bT, BATCH, H2);
    cudaEventRecord(evPrep2, 0);

    // side stream: coact1 overlaps fwd3
    cudaStreamWaitEvent(s_side, evPrep2, 0);
    gemm_co<<<dim3(H2 / 128, H1 / 128), blk, CO_SMEM, s_side>>>(
        a1bT, a2bT, coact1, H1, H2, BATCH);
    cudaEventRecord(evC1, s_side);

    // fwd3: logits = a2 @ W3^T + b3
    gemm_fwd<false><<<dim3((N_CLS + 127) / 128, BATCH / 128), blk, FWD_SMEM>>>(
        a2hi, a2lo, w3h, b3, logits, BATCH, N_CLS, H2);
    binT_k<<<dim3((N_CLS + 31) / 32, BATCH / 32), tb>>>(logits, lbT, BATCH, N_CLS);

    // coact2 on main stream
    gemm_co<<<dim3((N_CLS + 127) / 128, H2 / 128), blk, CO_SMEM>>>(
        a2bT, lbT, coact2, H2, N_CLS, BATCH);

    // join side stream
    cudaStreamWaitEvent(0, evC0, 0);
    cudaStreamWaitEvent(0, evC1, 0);
}

// round 13
// speedup vs baseline: 1.5915x; 1.0494x over previous
#include <cuda_runtime.h>
#include <cuda_bf16.h>
#include <cuda_fp16.h>
#include <stdint.h>

#define BATCH 8192
#define D_IN  1024
#define H1    2048
#define H2    2048
#define N_CLS 1000

// ---------------- scratch (device globals; no allocations allowed) ----------
__device__ float g_a1[(size_t)BATCH * H1];
__device__ float g_a2[(size_t)BATCH * H2];
__device__ __align__(256) __half g_xhi[(size_t)BATCH * D_IN];
__device__ __align__(256) __half g_xlo[(size_t)BATCH * D_IN];
__device__ __align__(256) __half g_a1hi[(size_t)BATCH * H1];
__device__ __align__(256) __half g_a1lo[(size_t)BATCH * H1];
__device__ __align__(256) __half g_a2hi[(size_t)BATCH * H2];
__device__ __align__(256) __half g_a2lo[(size_t)BATCH * H2];
__device__ __align__(256) __half g_w1h[(size_t)H1 * D_IN];
__device__ __align__(256) __half g_w2h[(size_t)H2 * H1];
__device__ __align__(256) __half g_w3h[(size_t)N_CLS * H2];
__device__ __align__(256) __nv_bfloat16 g_xbT[(size_t)D_IN * BATCH];
__device__ __align__(256) __nv_bfloat16 g_a1bT[(size_t)H1 * BATCH];
__device__ __align__(256) __nv_bfloat16 g_a2bT[(size_t)H2 * BATCH];
__device__ __align__(256) __nv_bfloat16 g_lbT[(size_t)N_CLS * BATCH];

// ---------------- PTX helpers (sm_80-portable) ------------------------------
__device__ __forceinline__ uint32_t su32(const void* p) {
    uint32_t a;
    asm("{ .reg .u64 t; cvta.to.shared.u64 t, %1; cvt.u32.u64 %0, t; }" : "=r"(a) : "l"(p));
    return a;
}
__device__ __forceinline__ void ldsm4(uint32_t* r, uint32_t a) {
    asm volatile("ldmatrix.sync.aligned.m8n8.x4.shared.b16 {%0,%1,%2,%3}, [%4];"
                 : "=r"(r[0]), "=r"(r[1]), "=r"(r[2]), "=r"(r[3]) : "r"(a));
}
__device__ __forceinline__ void ldsm2(uint32_t* r, uint32_t a) {
    asm volatile("ldmatrix.sync.aligned.m8n8.x2.shared.b16 {%0,%1}, [%2];"
                 : "=r"(r[0]), "=r"(r[1]) : "r"(a));
}
__device__ __forceinline__ void mma_bf(float* c, const uint32_t* a, const uint32_t* b) {
    asm volatile(
        "mma.sync.aligned.m16n8k16.row.col.f32.bf16.bf16.f32 "
        "{%0,%1,%2,%3}, {%4,%5,%6,%7}, {%8,%9}, {%0,%1,%2,%3};"
        : "+f"(c[0]), "+f"(c[1]), "+f"(c[2]), "+f"(c[3])
        : "r"(a[0]), "r"(a[1]), "r"(a[2]), "r"(a[3]), "r"(b[0]), "r"(b[1]));
}
__device__ __forceinline__ void mma_f16(float* c, const uint32_t* a, const uint32_t* b) {
    asm volatile(
        "mma.sync.aligned.m16n8k16.row.col.f32.f16.f16.f32 "
        "{%0,%1,%2,%3}, {%4,%5,%6,%7}, {%8,%9}, {%0,%1,%2,%3};"
        : "+f"(c[0]), "+f"(c[1]), "+f"(c[2]), "+f"(c[3])
        : "r"(a[0]), "r"(a[1]), "r"(a[2]), "r"(a[3]), "r"(b[0]), "r"(b[1]));
}
__device__ __forceinline__ void cpa(uint32_t d, const void* s, int nbytes) {
    asm volatile("cp.async.cg.shared.global [%0], [%1], 16, %2;"
                 :: "r"(d), "l"(s), "r"(nbytes) : "memory");
}
#define CP_COMMIT() asm volatile("cp.async.commit_group;" ::: "memory")
#define CP_WAIT0()  asm volatile("cp.async.wait_group 0;" ::: "memory")
#define CP_WAIT1()  asm volatile("cp.async.wait_group 1;" ::: "memory")

// Conflict-free tile layout: logical 128 rows x 4 chunks(16B) -> 64 phys rows x 128B,
// XOR swizzle kills ldmatrix bank conflicts.
__device__ __forceinline__ uint32_t tadr(int row, int ch) {
    return (uint32_t)((row >> 1) * 128 +
                      (((((row & 1) << 2) | ch) ^ ((row >> 1) & 7)) << 4));
}
__device__ __forceinline__ uint32_t pkh(__half a, __half b) {
    return (uint32_t)__half_as_ushort(a) | ((uint32_t)__half_as_ushort(b) << 16);
}

// ---------------- prepack: fp32 -> fp16 (weights) ----------------------------
__global__ void w16_k(const float* __restrict__ in, __half* __restrict__ out, size_t n4)
{
    size_t i = (size_t)blockIdx.x * blockDim.x + threadIdx.x;
    size_t stride = (size_t)gridDim.x * blockDim.x;
    for (; i < n4; i += stride) {
        float4 v = ((const float4*)in)[i];
        uint2 o;
        o.x = pkh(__float2half(v.x), __float2half(v.y));
        o.y = pkh(__float2half(v.z), __float2half(v.w));
        ((uint2*)out)[i] = o;
    }
}

// ---------------- fused postproc: read once -> fp16 hi, fp16 lo, bf16 binT ---
// in fp32 [R, C]; hi/lo fp16 [R, C]; bT bf16 [C, R] binarized. C % 32 == 0.
__global__ void post_k(const float* __restrict__ in, __half* __restrict__ hi,
                       __half* __restrict__ lo, __nv_bfloat16* __restrict__ bT,
                       int R, int C)
{
    __shared__ float t[32][33];
    const int c0 = blockIdx.x * 32, r0 = blockIdx.y * 32;
    const int tx = threadIdx.x, ty = threadIdx.y;  // 32 x 8
#pragma unroll
    for (int i = 0; i < 4; i++) {
        int r = r0 + ty + i * 8, c = c0 + tx;
        float v = in[(size_t)r * C + c];
        t[ty + i * 8][tx] = v;
        __half h = __float2half(v);
        hi[(size_t)r * C + c] = h;
        lo[(size_t)r * C + c] = __float2half(v - __half2float(h));
    }
    __syncthreads();
    const __nv_bfloat16 one = __float2bfloat16(1.f);
    const __nv_bfloat16 zero = __float2bfloat16(0.f);
#pragma unroll
    for (int i = 0; i < 4; i++) {
        int oc = c0 + ty + i * 8;
        bT[(size_t)oc * R + r0 + tx] = (t[tx][ty + i * 8] > 0.f) ? one : zero;
    }
}

// ---------------- binarize + transpose (logits only; ragged C) ---------------
__global__ void binT_k(const float* __restrict__ in, __nv_bfloat16* __restrict__ out,
                       int R, int C)
{
    __shared__ float t[32][33];
    const int c0 = blockIdx.x * 32, r0 = blockIdx.y * 32;
    const int tx = threadIdx.x, ty = threadIdx.y;  // 32 x 8
#pragma unroll
    for (int i = 0; i < 4; i++) {
        int r = r0 + ty + i * 8, c = c0 + tx;
        t[ty + i * 8][tx] = (c < C) ? in[(size_t)r * C + c] : 0.f;
    }
    __syncthreads();
    const __nv_bfloat16 one = __float2bfloat16(1.f);
    const __nv_bfloat16 zero = __float2bfloat16(0.f);
#pragma unroll
    for (int i = 0; i < 4; i++) {
        int oc = c0 + ty + i * 8;
        if (oc < C)
            out[(size_t)oc * R + r0 + tx] = (t[tx][ty + i * 8] > 0.f) ? one : zero;
    }
}

// ---------------- forward GEMM: fp16, A split (hi+lo), B single --------------
// C[M,N] = (Ahi+Alo) @ B^T + bias [+relu]. A [M,K] fp16 x2, B [N,K] fp16.
// Warp grid 4x2 (warp tile 32x64): A-redundancy 2, B-redundancy 4 — minimizes
// crossbar reads since A is the doubled (hi+lo) operand.
#define STAGES 3
#define FWD_STG 24576                 // Ah 8K | Al 8K | B 8K
#define FWD_SMEM (FWD_STG * STAGES)   // 72 KB -> 3 CTAs/SM
template <bool RELU>
__global__ void __launch_bounds__(256)
gemm_fwd(const __half* __restrict__ Ah, const __half* __restrict__ Al,
         const __half* __restrict__ B, const float* __restrict__ bias,
         float* __restrict__ C, int M, int N, int K)
{
    extern __shared__ char smem[];
    const uint32_t sb = su32(smem);

    const int tid = threadIdx.x;
    const int lane = tid & 31, wid = tid >> 5;
    const int warp_m = wid & 3, warp_n = wid >> 2;     // 4 x 2 warps, 32x64 each
    const int m0 = blockIdx.y * 128, n0 = blockIdx.x * 128;

    float acc[2][8][4];
#pragma unroll
    for (int mi = 0; mi < 2; mi++)
#pragma unroll
        for (int ni = 0; ni < 8; ni++)
#pragma unroll
            for (int e = 0; e < 4; e++) acc[mi][ni][e] = 0.f;

    const int T = K >> 5;

    auto issue = [&](int t) {
        const uint32_t s = sb + (t % STAGES) * FWD_STG;
        const int k0 = t * 32;
#pragma unroll
        for (int j = 0; j < 2; j++) {
            const int cid = j * 256 + tid;
            const int row = cid >> 2, ch = cid & 3;
            const uint32_t soff = tadr(row, ch);
            cpa(s + soff, Ah + (size_t)(m0 + row) * K + k0 + ch * 8, 16);
            cpa(s + 8192 + soff, Al + (size_t)(m0 + row) * K + k0 + ch * 8, 16);
            const int brow = n0 + row;
            const int ok = brow < N;
            cpa(s + 16384 + soff, B + (size_t)(ok ? brow : 0) * K + k0 + ch * 8, ok ? 16 : 0);
        }
        CP_COMMIT();
    };

    issue(0);
    issue(1);

    for (int t = 0; t < T; t++) {
        if (t == T - 1) CP_WAIT0(); else CP_WAIT1();
        __syncthreads();
        if (t + 2 < T) issue(t + 2);

        const uint32_t s = sb + (t % STAGES) * FWD_STG;
        const uint32_t sA = s, sAl = s + 8192, sB = s + 16384;

#pragma unroll
        for (int ks = 0; ks < 2; ks++) {
            uint32_t ah[2][4], al_[2][4];
#pragma unroll
            for (int mi = 0; mi < 2; mi++) {
                const int row = warp_m * 32 + mi * 16 + (lane & 15);
                const int ch = ks * 2 + (lane >> 4);
                const uint32_t off = tadr(row, ch);
                ldsm4(ah[mi], sA + off);
                ldsm4(al_[mi], sAl + off);
            }
#pragma unroll
            for (int np = 0; np < 4; np++) {     // B fragment pairs via ldsm4
                uint32_t bq[4];
                const int row = warp_n * 64 + (np * 2 + (lane >> 4)) * 8 + (lane & 7);
                const int ch = ks * 2 + ((lane >> 3) & 1);
                ldsm4(bq, sB + tadr(row, ch));
#pragma unroll
                for (int mi = 0; mi < 2; mi++) {
                    mma_f16(acc[mi][np * 2], ah[mi], bq);
                    mma_f16(acc[mi][np * 2 + 1], ah[mi], bq + 2);
                    mma_f16(acc[mi][np * 2], al_[mi], bq);
                    mma_f16(acc[mi][np * 2 + 1], al_[mi], bq + 2);
                }
            }
        }
    }

    // epilogue: bias (+relu), fp32 out
#pragma unroll
    for (int mi = 0; mi < 2; mi++) {
        const int r0 = m0 + warp_m * 32 + mi * 16 + (lane >> 2);
#pragma unroll
        for (int ni = 0; ni < 8; ni++) {
            const int col = n0 + warp_n * 64 + ni * 8 + (lane & 3) * 2;
            if (col < N) {
                const float b0 = __ldg(bias + col), b1 = __ldg(bias + col + 1);
                float2 v0 = make_float2(acc[mi][ni][0] + b0, acc[mi][ni][1] + b1);
                float2 v1 = make_float2(acc[mi][ni][2] + b0, acc[mi][ni][3] + b1);
                if (RELU) {
                    v0.x = fmaxf(v0.x, 0.f); v0.y = fmaxf(v0.y, 0.f);
                    v1.x = fmaxf(v1.x, 0.f); v1.y = fmaxf(v1.y, 0.f);
                }
                *(float2*)(C + (size_t)r0 * N + col) = v0;
                *(float2*)(C + (size_t)(r0 + 8) * N + col) = v1;
            }
        }
    }
}

// ---------------- coact GEMM: bf16 0/1, exact (R7-proven) --------------------
#define CO_STG 16384                  // A 8K | B 8K
#define CO_SMEM (CO_STG * STAGES)
__global__ void __launch_bounds__(256)
gemm_co(const __nv_bfloat16* __restrict__ A, const __nv_bfloat16* __restrict__ B,
        float* __restrict__ C, int M, int N, int K)
{
    extern __shared__ char smem[];
    const uint32_t sb = su32(smem);

    const int tid = threadIdx.x;
    const int lane = tid & 31, wid = tid >> 5;
    const int warp_m = wid & 1, warp_n = wid >> 1;
    const int m0 = blockIdx.y * 128, n0 = blockIdx.x * 128;

    float acc[4][4][4];
#pragma unroll
    for (int mi = 0; mi < 4; mi++)
#pragma unroll
        for (int ni = 0; ni < 4; ni++)
#pragma unroll
            for (int e = 0; e < 4; e++) acc[mi][ni][e] = 0.f;

    const int T = K >> 5;

    auto issue = [&](int t) {
        const uint32_t s = sb + (t % STAGES) * CO_STG;
        const int k0 = t * 32;
#pragma unroll
        for (int j = 0; j < 2; j++) {
            const int cid = j * 256 + tid;
            const int row = cid >> 2, ch = cid & 3;
            const uint32_t soff = tadr(row, ch);
            cpa(s + soff, A + (size_t)(m0 + row) * K + k0 + ch * 8, 16);
            const int brow = n0 + row;
            const int ok = brow < N;
            cpa(s + 8192 + soff, B + (size_t)(ok ? brow : 0) * K + k0 + ch * 8, ok ? 16 : 0);
        }
        CP_COMMIT();
    };

    issue(0);
    issue(1);

    for (int t = 0; t < T; t++) {
        if (t == T - 1) CP_WAIT0(); else CP_WAIT1();
        __syncthreads();
        if (t + 2 < T) issue(t + 2);

        const uint32_t s = sb + (t % STAGES) * CO_STG;
        const uint32_t sA = s, sB = s + 8192;

#pragma unroll
        for (int ks = 0; ks < 2; ks++) {
            uint32_t a[4][4], bq[4][2];
#pragma unroll
            for (int mi = 0; mi < 4; mi++) {
                const int row = warp_m * 64 + mi * 16 + (lane & 15);
                const int ch = ks * 2 + (lane >> 4);
                ldsm4(a[mi], sA + tadr(row, ch));
            }
#pragma unroll
            for (int ni = 0; ni < 4; ni++) {
                const int row = warp_n * 32 + ni * 8 + (lane & 7);
                const int ch = ks * 2 + ((lane >> 3) & 1);
                ldsm2(bq[ni], sB + tadr(row, ch));
            }
#pragma unroll
            for (int mi = 0; mi < 4; mi++)
#pragma unroll
                for (int ni = 0; ni < 4; ni++)
                    mma_bf(acc[mi][ni], a[mi], bq[ni]);
        }
    }

#pragma unroll
    for (int mi = 0; mi < 4; mi++) {
        const int r0 = m0 + warp_m * 64 + mi * 16 + (lane >> 2);
#pragma unroll
        for (int ni = 0; ni < 4; ni++) {
            const int col = n0 + warp_n * 32 + ni * 8 + (lane & 3) * 2;
            if (col < N) {
                *(float2*)(C + (size_t)r0 * N + col) =
                    make_float2(acc[mi][ni][0], acc[mi][ni][1]);
                *(float2*)(C + (size_t)(r0 + 8) * N + col) =
                    make_float2(acc[mi][ni][2], acc[mi][ni][3]);
            }
        }
    }
}

// ---------------- launch -----------------------------------------------------
extern "C" void kernel_launch(void* const* d_in, const int* in_sizes, int n_in,
                              void* d_out, int out_size)
{
    const float* x  = (const float*)d_in[0];
    const float* W1 = (const float*)d_in[1];
    const float* b1 = (const float*)d_in[2];
    const float* W2 = (const float*)d_in[3];
    const float* b2 = (const float*)d_in[4];
    const float* W3 = (const float*)d_in[5];
    const float* b3 = (const float*)d_in[6];

    float* out    = (float*)d_out;
    float* logits = out;
    float* coact0 = logits + (size_t)BATCH * N_CLS;
    float* coact1 = coact0 + (size_t)D_IN * H1;
    float* coact2 = coact1 + (size_t)H1 * H2;

    float *a1, *a2;
    __half *xhi, *xlo, *a1hi, *a1lo, *a2hi, *a2lo, *w1h, *w2h, *w3h;
    __nv_bfloat16 *xbT, *a1bT, *a2bT, *lbT;
    cudaGetSymbolAddress((void**)&a1, g_a1);
    cudaGetSymbolAddress((void**)&a2, g_a2);
    cudaGetSymbolAddress((void**)&xhi, g_xhi);   cudaGetSymbolAddress((void**)&xlo, g_xlo);
    cudaGetSymbolAddress((void**)&a1hi, g_a1hi); cudaGetSymbolAddress((void**)&a1lo, g_a1lo);
    cudaGetSymbolAddress((void**)&a2hi, g_a2hi); cudaGetSymbolAddress((void**)&a2lo, g_a2lo);
    cudaGetSymbolAddress((void**)&w1h, g_w1h);
    cudaGetSymbolAddress((void**)&w2h, g_w2h);
    cudaGetSymbolAddress((void**)&w3h, g_w3h);
    cudaGetSymbolAddress((void**)&xbT, g_xbT);   cudaGetSymbolAddress((void**)&a1bT, g_a1bT);
    cudaGetSymbolAddress((void**)&a2bT, g_a2bT); cudaGetSymbolAddress((void**)&lbT, g_lbT);

    static bool s_init = false;
    static cudaStream_t s_side;
    static cudaEvent_t evFork, evW23, evPrep1, evPrep2, evC0, evC1;
    if (!s_init) {
        cudaStreamCreateWithFlags(&s_side, cudaStreamNonBlocking);
        cudaEventCreateWithFlags(&evFork, cudaEventDisableTiming);
        cudaEventCreateWithFlags(&evW23, cudaEventDisableTiming);
        cudaEventCreateWithFlags(&evPrep1, cudaEventDisableTiming);
        cudaEventCreateWithFlags(&evPrep2, cudaEventDisableTiming);
        cudaEventCreateWithFlags(&evC0, cudaEventDisableTiming);
        cudaEventCreateWithFlags(&evC1, cudaEventDisableTiming);
        cudaFuncSetAttribute(gemm_fwd<true>, cudaFuncAttributeMaxDynamicSharedMemorySize, FWD_SMEM);
        cudaFuncSetAttribute(gemm_fwd<false>, cudaFuncAttributeMaxDynamicSharedMemorySize, FWD_SMEM);
        cudaFuncSetAttribute(gemm_co, cudaFuncAttributeMaxDynamicSharedMemorySize, CO_SMEM);
        s_init = true;
    }

    const dim3 blk(256);
    const dim3 tb(32, 8);

    // capture-legal fork: side stream's FIRST op waits on an event from stream 0
    cudaEventRecord(evFork, 0);
    cudaStreamWaitEvent(s_side, evFork, 0);

    // main stream: prepack needed for fwd1 (x hi/lo + xbT in one pass, W1 fp16)
    post_k<<<dim3(D_IN / 32, BATCH / 32), tb>>>(x, xhi, xlo, xbT, BATCH, D_IN);
    w16_k<<<1024, 256>>>(W1, w1h, (size_t)H1 * D_IN / 4);

    // side stream: W2/W3 fp16, overlapping fwd1
    w16_k<<<1024, 256, 0, s_side>>>(W2, w2h, (size_t)H2 * H1 / 4);
    w16_k<<<1024, 256, 0, s_side>>>(W3, w3h, (size_t)N_CLS * H2 / 4);
    cudaEventRecord(evW23, s_side);

    // fwd1: a1 = relu(x @ W1^T + b1), fused postproc
    gemm_fwd<true><<<dim3(H1 / 128, BATCH / 128), blk, FWD_SMEM>>>(
        xhi, xlo, w1h, b1, a1, BATCH, H1, D_IN);
    post_k<<<dim3(H1 / 32, BATCH / 32), tb>>>(a1, a1hi, a1lo, a1bT, BATCH, H1);
    cudaEventRecord(evPrep1, 0);

    // side stream: coact0 overlaps fwd2
    cudaStreamWaitEvent(s_side, evPrep1, 0);
    gemm_co<<<dim3(H1 / 128, D_IN / 128), blk, CO_SMEM, s_side>>>(
        xbT, a1bT, coact0, D_IN, H1, BATCH);
    cudaEventRecord(evC0, s_side);

    // fwd2: a2 = relu(a1 @ W2^T + b2)  (needs w2 from side stream)
    cudaStreamWaitEvent(0, evW23, 0);
    gemm_fwd<true><<<dim3(H2 / 128, BATCH / 128), blk, FWD_SMEM>>>(
        a1hi, a1lo, w2h, b2, a2, BATCH, H2, H1);
    post_k<<<dim3(H2 / 32, BATCH / 32), tb>>>(a2, a2hi, a2lo, a2bT, BATCH, H2);
    cudaEventRecord(evPrep2, 0);

    // side stream: coact1 overlaps fwd3
    cudaStreamWaitEvent(s_side, evPrep2, 0);
    gemm_co<<<dim3(H2 / 128, H1 / 128), blk, CO_SMEM, s_side>>>(
        a1bT, a2bT, coact1, H1, H2, BATCH);
    cudaEventRecord(evC1, s_side);

    // fwd3: logits = a2 @ W3^T + b3
    gemm_fwd<false><<<dim3((N_CLS + 127) / 128, BATCH / 128), blk, FWD_SMEM>>>(
        a2hi, a2lo, w3h, b3, logits, BATCH, N_CLS, H2);
    binT_k<<<dim3((N_CLS + 31) / 32, BATCH / 32), tb>>>(logits, lbT, BATCH, N_CLS);

    // coact2 on main stream
    gemm_co<<<dim3((N_CLS + 127) / 128, H2 / 128), blk, CO_SMEM>>>(
        a2bT, lbT, coact2, H2, N_CLS, BATCH);

    // join side stream
    cudaStreamWaitEvent(0, evC0, 0);
    cudaStreamWaitEvent(0, evC1, 0);
}

// round 14
// speedup vs baseline: 1.6043x; 1.0081x over previous
#include <cuda_runtime.h>
#include <cuda_bf16.h>
#include <cuda_fp16.h>
#include <stdint.h>

#define BATCH 8192
#define D_IN  1024
#define H1    2048
#define H2    2048
#define N_CLS 1000
#define HALF_B 4096

// ---------------- scratch (device globals; no allocations allowed) ----------
__device__ float g_a1[(size_t)BATCH * H1];
__device__ float g_a2[(size_t)BATCH * H2];
__device__ __align__(256) __half g_xhi[(size_t)BATCH * D_IN];
__device__ __align__(256) __half g_xlo[(size_t)BATCH * D_IN];
__device__ __align__(256) __half g_a1hi[(size_t)BATCH * H1];
__device__ __align__(256) __half g_a1lo[(size_t)BATCH * H1];
__device__ __align__(256) __half g_a2hi[(size_t)BATCH * H2];
__device__ __align__(256) __half g_a2lo[(size_t)BATCH * H2];
__device__ __align__(256) __half g_w1h[(size_t)H1 * D_IN];
__device__ __align__(256) __half g_w2h[(size_t)H2 * H1];
__device__ __align__(256) __half g_w3h[(size_t)N_CLS * H2];
__device__ __align__(256) __nv_bfloat16 g_xbT[(size_t)D_IN * BATCH];
__device__ __align__(256) __nv_bfloat16 g_a1bT[(size_t)H1 * BATCH];
__device__ __align__(256) __nv_bfloat16 g_a2bT[(size_t)H2 * BATCH];
__device__ __align__(256) __nv_bfloat16 g_lbT[(size_t)N_CLS * BATCH];

// ---------------- PTX helpers (sm_80-portable) ------------------------------
__device__ __forceinline__ uint32_t su32(const void* p) {
    uint32_t a;
    asm("{ .reg .u64 t; cvta.to.shared.u64 t, %1; cvt.u32.u64 %0, t; }" : "=r"(a) : "l"(p));
    return a;
}
__device__ __forceinline__ void ldsm4(uint32_t* r, uint32_t a) {
    asm volatile("ldmatrix.sync.aligned.m8n8.x4.shared.b16 {%0,%1,%2,%3}, [%4];"
                 : "=r"(r[0]), "=r"(r[1]), "=r"(r[2]), "=r"(r[3]) : "r"(a));
}
__device__ __forceinline__ void mma_bf(float* c, const uint32_t* a, const uint32_t* b) {
    asm volatile(
        "mma.sync.aligned.m16n8k16.row.col.f32.bf16.bf16.f32 "
        "{%0,%1,%2,%3}, {%4,%5,%6,%7}, {%8,%9}, {%0,%1,%2,%3};"
        : "+f"(c[0]), "+f"(c[1]), "+f"(c[2]), "+f"(c[3])
        : "r"(a[0]), "r"(a[1]), "r"(a[2]), "r"(a[3]), "r"(b[0]), "r"(b[1]));
}
__device__ __forceinline__ void mma_f16(float* c, const uint32_t* a, const uint32_t* b) {
    asm volatile(
        "mma.sync.aligned.m16n8k16.row.col.f32.f16.f16.f32 "
        "{%0,%1,%2,%3}, {%4,%5,%6,%7}, {%8,%9}, {%0,%1,%2,%3};"
        : "+f"(c[0]), "+f"(c[1]), "+f"(c[2]), "+f"(c[3])
        : "r"(a[0]), "r"(a[1]), "r"(a[2]), "r"(a[3]), "r"(b[0]), "r"(b[1]));
}
__device__ __forceinline__ void cpa(uint32_t d, const void* s, int nbytes) {
    asm volatile("cp.async.cg.shared.global [%0], [%1], 16, %2;"
                 :: "r"(d), "l"(s), "r"(nbytes) : "memory");
}
#define CP_COMMIT() asm volatile("cp.async.commit_group;" ::: "memory")
#define CP_WAIT0()  asm volatile("cp.async.wait_group 0;" ::: "memory")
#define CP_WAIT1()  asm volatile("cp.async.wait_group 1;" ::: "memory")

// Conflict-free tile layout (verified): logical row x 16B-chunk -> swizzled offset.
__device__ __forceinline__ uint32_t tadr(int row, int ch) {
    return (uint32_t)((row >> 1) * 128 +
                      (((((row & 1) << 2) | ch) ^ ((row >> 1) & 7)) << 4));
}
__device__ __forceinline__ uint32_t pkh(__half a, __half b) {
    return (uint32_t)__half_as_ushort(a) | ((uint32_t)__half_as_ushort(b) << 16);
}

// ---------------- prepack: fp32 -> fp16 (weights) ----------------------------
__global__ void w16_k(const float* __restrict__ in, __half* __restrict__ out, size_t n4)
{
    size_t i = (size_t)blockIdx.x * blockDim.x + threadIdx.x;
    size_t stride = (size_t)gridDim.x * blockDim.x;
    for (; i < n4; i += stride) {
        float4 v = ((const float4*)in)[i];
        uint2 o;
        o.x = pkh(__float2half(v.x), __float2half(v.y));
        o.y = pkh(__float2half(v.z), __float2half(v.w));
        ((uint2*)out)[i] = o;
    }
}

// ---------------- fused postproc: read once -> fp16 hi, fp16 lo, bf16 binT ---
__global__ void post_k(const float* __restrict__ in, __half* __restrict__ hi,
                       __half* __restrict__ lo, __nv_bfloat16* __restrict__ bT,
                       int R, int C)
{
    __shared__ float t[32][33];
    const int c0 = blockIdx.x * 32, r0 = blockIdx.y * 32;
    const int tx = threadIdx.x, ty = threadIdx.y;  // 32 x 8
#pragma unroll
    for (int i = 0; i < 4; i++) {
        int r = r0 + ty + i * 8, c = c0 + tx;
        float v = in[(size_t)r * C + c];
        t[ty + i * 8][tx] = v;
        __half h = __float2half(v);
        hi[(size_t)r * C + c] = h;
        lo[(size_t)r * C + c] = __float2half(v - __half2float(h));
    }
    __syncthreads();
    const __nv_bfloat16 one = __float2bfloat16(1.f);
    const __nv_bfloat16 zero = __float2bfloat16(0.f);
#pragma unroll
    for (int i = 0; i < 4; i++) {
        int oc = c0 + ty + i * 8;
        bT[(size_t)oc * R + r0 + tx] = (t[tx][ty + i * 8] > 0.f) ? one : zero;
    }
}

// ---------------- binarize + transpose (logits; ragged C, R = out stride) ----
__global__ void binT_k(const float* __restrict__ in, __nv_bfloat16* __restrict__ out,
                       int R, int C)
{
    __shared__ float t[32][33];
    const int c0 = blockIdx.x * 32, r0 = blockIdx.y * 32;
    const int tx = threadIdx.x, ty = threadIdx.y;  // 32 x 8
#pragma unroll
    for (int i = 0; i < 4; i++) {
        int r = r0 + ty + i * 8, c = c0 + tx;
        t[ty + i * 8][tx] = (c < C) ? in[(size_t)r * C + c] : 0.f;
    }
    __syncthreads();
    const __nv_bfloat16 one = __float2bfloat16(1.f);
    const __nv_bfloat16 zero = __float2bfloat16(0.f);
#pragma unroll
    for (int i = 0; i < 4; i++) {
        int oc = c0 + ty + i * 8;
        if (oc < C)
            out[(size_t)oc * R + r0 + tx] = (t[tx][ty + i * 8] > 0.f) ? one : zero;
    }
}

// ---------------- forward GEMM: fp16, A split (hi+lo), warp grid 4x2 ---------
#define STAGES 3
#define FWD_STG 24576
#define FWD_SMEM (FWD_STG * STAGES)   // 72 KB -> 3 CTAs/SM
template <bool RELU>
__global__ void __launch_bounds__(256)
gemm_fwd(const __half* __restrict__ Ah, const __half* __restrict__ Al,
         const __half* __restrict__ B, const float* __restrict__ bias,
         float* __restrict__ C, int M, int N, int K)
{
    extern __shared__ char smem[];
    const uint32_t sb = su32(smem);

    const int tid = threadIdx.x;
    const int lane = tid & 31, wid = tid >> 5;
    const int warp_m = wid & 3, warp_n = wid >> 2;     // 4 x 2 warps, 32x64 each
    const int m0 = blockIdx.y * 128, n0 = blockIdx.x * 128;

    float acc[2][8][4];
#pragma unroll
    for (int mi = 0; mi < 2; mi++)
#pragma unroll
        for (int ni = 0; ni < 8; ni++)
#pragma unroll
            for (int e = 0; e < 4; e++) acc[mi][ni][e] = 0.f;

    const int T = K >> 5;

    auto issue = [&](int t) {
        const uint32_t s = sb + (t % STAGES) * FWD_STG;
        const int k0 = t * 32;
#pragma unroll
        for (int j = 0; j < 2; j++) {
            const int cid = j * 256 + tid;
            const int row = cid >> 2, ch = cid & 3;
            const uint32_t soff = tadr(row, ch);
            cpa(s + soff, Ah + (size_t)(m0 + row) * K + k0 + ch * 8, 16);
            cpa(s + 8192 + soff, Al + (size_t)(m0 + row) * K + k0 + ch * 8, 16);
            const int brow = n0 + row;
            const int ok = brow < N;
            cpa(s + 16384 + soff, B + (size_t)(ok ? brow : 0) * K + k0 + ch * 8, ok ? 16 : 0);
        }
        CP_COMMIT();
    };

    issue(0);
    issue(1);

    for (int t = 0; t < T; t++) {
        if (t == T - 1) CP_WAIT0(); else CP_WAIT1();
        __syncthreads();
        if (t + 2 < T) issue(t + 2);

        const uint32_t s = sb + (t % STAGES) * FWD_STG;
        const uint32_t sA = s, sAl = s + 8192, sB = s + 16384;

#pragma unroll
        for (int ks = 0; ks < 2; ks++) {
            uint32_t ah[2][4], al_[2][4];
#pragma unroll
            for (int mi = 0; mi < 2; mi++) {
                const int row = warp_m * 32 + mi * 16 + (lane & 15);
                const int ch = ks * 2 + (lane >> 4);
                const uint32_t off = tadr(row, ch);
                ldsm4(ah[mi], sA + off);
                ldsm4(al_[mi], sAl + off);
            }
#pragma unroll
            for (int np = 0; np < 4; np++) {
                uint32_t bq[4];
                const int row = warp_n * 64 + (np * 2 + (lane >> 4)) * 8 + (lane & 7);
                const int ch = ks * 2 + ((lane >> 3) & 1);
                ldsm4(bq, sB + tadr(row, ch));
#pragma unroll
                for (int mi = 0; mi < 2; mi++) {
                    mma_f16(acc[mi][np * 2], ah[mi], bq);
                    mma_f16(acc[mi][np * 2 + 1], ah[mi], bq + 2);
                    mma_f16(acc[mi][np * 2], al_[mi], bq);
                    mma_f16(acc[mi][np * 2 + 1], al_[mi], bq + 2);
                }
            }
        }
    }

#pragma unroll
    for (int mi = 0; mi < 2; mi++) {
        const int r0 = m0 + warp_m * 32 + mi * 16 + (lane >> 2);
#pragma unroll
        for (int ni = 0; ni < 8; ni++) {
            const int col = n0 + warp_n * 64 + ni * 8 + (lane & 3) * 2;
            if (col < N) {
                const float b0 = __ldg(bias + col), b1 = __ldg(bias + col + 1);
                float2 v0 = make_float2(acc[mi][ni][0] + b0, acc[mi][ni][1] + b1);
                float2 v1 = make_float2(acc[mi][ni][2] + b0, acc[mi][ni][3] + b1);
                if (RELU) {
                    v0.x = fmaxf(v0.x, 0.f); v0.y = fmaxf(v0.y, 0.f);
                    v1.x = fmaxf(v1.x, 0.f); v1.y = fmaxf(v1.y, 0.f);
                }
                *(float2*)(C + (size_t)r0 * N + col) = v0;
                *(float2*)(C + (size_t)(r0 + 8) * N + col) = v1;
            }
        }
    }
}

// ---------------- coact GEMM: bf16 0/1, exact; ldk = row stride --------------
// ACCUM: C += partial (exact integer partial sums -> fp32 add exact).
#define CO_STG 16384
#define CO_SMEM (CO_STG * STAGES)
template <bool ACCUM>
__global__ void __launch_bounds__(256)
gemm_co(const __nv_bfloat16* __restrict__ A, const __nv_bfloat16* __restrict__ B,
        float* __restrict__ C, int M, int N, int ldk, int K)
{
    extern __shared__ char smem[];
    const uint32_t sb = su32(smem);

    const int tid = threadIdx.x;
    const int lane = tid & 31, wid = tid >> 5;
    const int warp_m = wid & 1, warp_n = wid >> 1;     // 2 x 4, warp tile 64x32
    const int m0 = blockIdx.y * 128, n0 = blockIdx.x * 128;

    float acc[4][4][4];
#pragma unroll
    for (int mi = 0; mi < 4; mi++)
#pragma unroll
        for (int ni = 0; ni < 4; ni++)
#pragma unroll
            for (int e = 0; e < 4; e++) acc[mi][ni][e] = 0.f;

    const int T = K >> 5;

    auto issue = [&](int t) {
        const uint32_t s = sb + (t % STAGES) * CO_STG;
        const int k0 = t * 32;
#pragma unroll
        for (int j = 0; j < 2; j++) {
            const int cid = j * 256 + tid;
            const int row = cid >> 2, ch = cid & 3;
            const uint32_t soff = tadr(row, ch);
            cpa(s + soff, A + (size_t)(m0 + row) * ldk + k0 + ch * 8, 16);
            const int brow = n0 + row;
            const int ok = brow < N;
            cpa(s + 8192 + soff, B + (size_t)(ok ? brow : 0) * ldk + k0 + ch * 8, ok ? 16 : 0);
        }
        CP_COMMIT();
    };

    issue(0);
    issue(1);

    for (int t = 0; t < T; t++) {
        if (t == T - 1) CP_WAIT0(); else CP_WAIT1();
        __syncthreads();
        if (t + 2 < T) issue(t + 2);

        const uint32_t s = sb + (t % STAGES) * CO_STG;
        const uint32_t sA = s, sB = s + 8192;

#pragma unroll
        for (int ks = 0; ks < 2; ks++) {
            uint32_t a[4][4];
#pragma unroll
            for (int mi = 0; mi < 4; mi++) {
                const int row = warp_m * 64 + mi * 16 + (lane & 15);
                const int ch = ks * 2 + (lane >> 4);
                ldsm4(a[mi], sA + tadr(row, ch));
            }
#pragma unroll
            for (int np = 0; np < 2; np++) {     // B pairs via ldsm4
                uint32_t bq[4];
                const int row = warp_n * 32 + (np * 2 + (lane >> 4)) * 8 + (lane & 7);
                const int ch = ks * 2 + ((lane >> 3) & 1);
                ldsm4(bq, sB + tadr(row, ch));
#pragma unroll
                for (int mi = 0; mi < 4; mi++) {
                    mma_bf(acc[mi][np * 2], a[mi], bq);
                    mma_bf(acc[mi][np * 2 + 1], a[mi], bq + 2);
                }
            }
        }
    }

#pragma unroll
    for (int mi = 0; mi < 4; mi++) {
        const int r0 = m0 + warp_m * 64 + mi * 16 + (lane >> 2);
#pragma unroll
        for (int ni = 0; ni < 4; ni++) {
            const int col = n0 + warp_n * 32 + ni * 8 + (lane & 3) * 2;
            if (col < N) {
                float2 v0 = make_float2(acc[mi][ni][0], acc[mi][ni][1]);
                float2 v1 = make_float2(acc[mi][ni][2], acc[mi][ni][3]);
                if (ACCUM) {
                    float2 o0 = *(float2*)(C + (size_t)r0 * N + col);
                    float2 o1 = *(float2*)(C + (size_t)(r0 + 8) * N + col);
                    v0.x += o0.x; v0.y += o0.y; v1.x += o1.x; v1.y += o1.y;
                }
                *(float2*)(C + (size_t)r0 * N + col) = v0;
                *(float2*)(C + (size_t)(r0 + 8) * N + col) = v1;
            }
        }
    }
}

// ---------------- launch -----------------------------------------------------
extern "C" void kernel_launch(void* const* d_in, const int* in_sizes, int n_in,
                              void* d_out, int out_size)
{
    const float* x  = (const float*)d_in[0];
    const float* W1 = (const float*)d_in[1];
    const float* b1 = (const float*)d_in[2];
    const float* W2 = (const float*)d_in[3];
    const float* b2 = (const float*)d_in[4];
    const float* W3 = (const float*)d_in[5];
    const float* b3 = (const float*)d_in[6];

    float* out    = (float*)d_out;
    float* logits = out;
    float* coact0 = logits + (size_t)BATCH * N_CLS;
    float* coact1 = coact0 + (size_t)D_IN * H1;
    float* coact2 = coact1 + (size_t)H1 * H2;

    float *a1, *a2;
    __half *xhi, *xlo, *a1hi, *a1lo, *a2hi, *a2lo, *w1h, *w2h, *w3h;
    __nv_bfloat16 *xbT, *a1bT, *a2bT, *lbT;
    cudaGetSymbolAddress((void**)&a1, g_a1);
    cudaGetSymbolAddress((void**)&a2, g_a2);
    cudaGetSymbolAddress((void**)&xhi, g_xhi);   cudaGetSymbolAddress((void**)&xlo, g_xlo);
    cudaGetSymbolAddress((void**)&a1hi, g_a1hi); cudaGetSymbolAddress((void**)&a1lo, g_a1lo);
    cudaGetSymbolAddress((void**)&a2hi, g_a2hi); cudaGetSymbolAddress((void**)&a2lo, g_a2lo);
    cudaGetSymbolAddress((void**)&w1h, g_w1h);
    cudaGetSymbolAddress((void**)&w2h, g_w2h);
    cudaGetSymbolAddress((void**)&w3h, g_w3h);
    cudaGetSymbolAddress((void**)&xbT, g_xbT);   cudaGetSymbolAddress((void**)&a1bT, g_a1bT);
    cudaGetSymbolAddress((void**)&a2bT, g_a2bT); cudaGetSymbolAddress((void**)&lbT, g_lbT);

    static bool s_init = false;
    static cudaStream_t s_side;
    static cudaEvent_t evFork, evW23, evPrep1, evPrep2, evC0, evC1, evL3a, evC2a;
    if (!s_init) {
        cudaStreamCreateWithFlags(&s_side, cudaStreamNonBlocking);
        cudaEventCreateWithFlags(&evFork, cudaEventDisableTiming);
        cudaEventCreateWithFlags(&evW23, cudaEventDisableTiming);
        cudaEventCreateWithFlags(&evPrep1, cudaEventDisableTiming);
        cudaEventCreateWithFlags(&evPrep2, cudaEventDisableTiming);
        cudaEventCreateWithFlags(&evC0, cudaEventDisableTiming);
        cudaEventCreateWithFlags(&evC1, cudaEventDisableTiming);
        cudaEventCreateWithFlags(&evL3a, cudaEventDisableTiming);
        cudaEventCreateWithFlags(&evC2a, cudaEventDisableTiming);
        cudaFuncSetAttribute(gemm_fwd<true>, cudaFuncAttributeMaxDynamicSharedMemorySize, FWD_SMEM);
        cudaFuncSetAttribute(gemm_fwd<false>, cudaFuncAttributeMaxDynamicSharedMemorySize, FWD_SMEM);
        cudaFuncSetAttribute(gemm_co<false>, cudaFuncAttributeMaxDynamicSharedMemorySize, CO_SMEM);
        cudaFuncSetAttribute(gemm_co<true>, cudaFuncAttributeMaxDynamicSharedMemorySize, CO_SMEM);
        s_init = true;
    }

    const dim3 blk(256);
    const dim3 tb(32, 8);

    // capture-legal fork
    cudaEventRecord(evFork, 0);
    cudaStreamWaitEvent(s_side, evFork, 0);

    // main: prepack for fwd1
    post_k<<<dim3(D_IN / 32, BATCH / 32), tb>>>(x, xhi, xlo, xbT, BATCH, D_IN);
    w16_k<<<1024, 256>>>(W1, w1h, (size_t)H1 * D_IN / 4);

    // side: W2/W3 fp16 overlap fwd1
    w16_k<<<1024, 256, 0, s_side>>>(W2, w2h, (size_t)H2 * H1 / 4);
    w16_k<<<1024, 256, 0, s_side>>>(W3, w3h, (size_t)N_CLS * H2 / 4);
    cudaEventRecord(evW23, s_side);

    // fwd1 + postproc
    gemm_fwd<true><<<dim3(H1 / 128, BATCH / 128), blk, FWD_SMEM>>>(
        xhi, xlo, w1h, b1, a1, BATCH, H1, D_IN);
    post_k<<<dim3(H1 / 32, BATCH / 32), tb>>>(a1, a1hi, a1lo, a1bT, BATCH, H1);
    cudaEventRecord(evPrep1, 0);

    // side: coact0 overlaps fwd2
    cudaStreamWaitEvent(s_side, evPrep1, 0);
    gemm_co<false><<<dim3(H1 / 128, D_IN / 128), blk, CO_SMEM, s_side>>>(
        xbT, a1bT, coact0, D_IN, H1, BATCH, BATCH);
    cudaEventRecord(evC0, s_side);

    // fwd2 + postproc
    cudaStreamWaitEvent(0, evW23, 0);
    gemm_fwd<true><<<dim3(H2 / 128, BATCH / 128), blk, FWD_SMEM>>>(
        a1hi, a1lo, w2h, b2, a2, BATCH, H2, H1);
    post_k<<<dim3(H2 / 32, BATCH / 32), tb>>>(a2, a2hi, a2lo, a2bT, BATCH, H2);
    cudaEventRecord(evPrep2, 0);

    // side: coact1 overlaps fwd3
    cudaStreamWaitEvent(s_side, evPrep2, 0);
    gemm_co<false><<<dim3(H2 / 128, H1 / 128), blk, CO_SMEM, s_side>>>(
        a1bT, a2bT, coact1, H1, H2, BATCH, BATCH);
    cudaEventRecord(evC1, s_side);

    // fwd3a: logits rows [0, HALF_B)
    gemm_fwd<false><<<dim3((N_CLS + 127) / 128, HALF_B / 128), blk, FWD_SMEM>>>(
        a2hi, a2lo, w3h, b3, logits, HALF_B, N_CLS, H2);
    cudaEventRecord(evL3a, 0);

    // side: binT(logits a) + coact2a (init) overlap fwd3b
    cudaStreamWaitEvent(s_side, evL3a, 0);
    binT_k<<<dim3((N_CLS + 31) / 32, HALF_B / 32), tb, 0, s_side>>>(
        logits, lbT, BATCH, N_CLS);
    gemm_co<false><<<dim3((N_CLS + 127) / 128, H2 / 128), blk, CO_SMEM, s_side>>>(
        a2bT, lbT, coact2, H2, N_CLS, BATCH, HALF_B);
    cudaEventRecord(evC2a, s_side);

    // fwd3b: logits rows [HALF_B, BATCH)
    gemm_fwd<false><<<dim3((N_CLS + 127) / 128, HALF_B / 128), blk, FWD_SMEM>>>(
        a2hi + (size_t)HALF_B * H2, a2lo + (size_t)HALF_B * H2, w3h, b3,
        logits + (size_t)HALF_B * N_CLS, HALF_B, N_CLS, H2);
    binT_k<<<dim3((N_CLS + 31) / 32, HALF_B / 32), tb>>>(
        logits + (size_t)HALF_B * N_CLS, lbT + HALF_B, BATCH, N_CLS);

    // coact2b: accumulate second K-half (waits coact2a)
    cudaStreamWaitEvent(0, evC2a, 0);
    gemm_co<true><<<dim3((N_CLS + 127) / 128, H2 / 128), blk, CO_SMEM>>>(
        a2bT + HALF_B, lbT + HALF_B, coact2, H2, N_CLS, BATCH, HALF_B);

    // join side stream
    cudaStreamWaitEvent(0, evC0, 0);
    cudaStreamWaitEvent(0, evC1, 0);
}

// round 15
// speedup vs baseline: 2.0895x; 1.3025x over previous
#include <cuda_runtime.h>
#include <cuda_bf16.h>
#include <cuda_fp16.h>
#include <stdint.h>

#define BATCH 8192
#define D_IN  1024
#define H1    2048
#define H2    2048
#define N_CLS 1000
#define HALF_B 4096

// ---------------- scratch (device globals; no allocations allowed) ----------
__device__ float g_a1[(size_t)BATCH * H1];
__device__ float g_a2[(size_t)BATCH * H2];
__device__ __align__(256) __half g_xh[(size_t)BATCH * D_IN];
__device__ __align__(256) __half g_a1h[(size_t)BATCH * H1];
__device__ __align__(256) __half g_a2h[(size_t)BATCH * H2];
__device__ __align__(256) __half g_w1h[(size_t)H1 * D_IN];
__device__ __align__(256) __half g_w2h[(size_t)H2 * H1];
__device__ __align__(256) __half g_w3h[(size_t)N_CLS * H2];
__device__ __align__(256) __nv_bfloat16 g_xbT[(size_t)D_IN * BATCH];
__device__ __align__(256) __nv_bfloat16 g_a1bT[(size_t)H1 * BATCH];
__device__ __align__(256) __nv_bfloat16 g_a2bT[(size_t)H2 * BATCH];
__device__ __align__(256) __nv_bfloat16 g_lbT[(size_t)N_CLS * BATCH];

// ---------------- PTX helpers (sm_80-portable) ------------------------------
__device__ __forceinline__ uint32_t su32(const void* p) {
    uint32_t a;
    asm("{ .reg .u64 t; cvta.to.shared.u64 t, %1; cvt.u32.u64 %0, t; }" : "=r"(a) : "l"(p));
    return a;
}
__device__ __forceinline__ void ldsm4(uint32_t* r, uint32_t a) {
    asm volatile("ldmatrix.sync.aligned.m8n8.x4.shared.b16 {%0,%1,%2,%3}, [%4];"
                 : "=r"(r[0]), "=r"(r[1]), "=r"(r[2]), "=r"(r[3]) : "r"(a));
}
__device__ __forceinline__ void mma_bf(float* c, const uint32_t* a, const uint32_t* b) {
    asm volatile(
        "mma.sync.aligned.m16n8k16.row.col.f32.bf16.bf16.f32 "
        "{%0,%1,%2,%3}, {%4,%5,%6,%7}, {%8,%9}, {%0,%1,%2,%3};"
        : "+f"(c[0]), "+f"(c[1]), "+f"(c[2]), "+f"(c[3])
        : "r"(a[0]), "r"(a[1]), "r"(a[2]), "r"(a[3]), "r"(b[0]), "r"(b[1]));
}
__device__ __forceinline__ void mma_f16(float* c, const uint32_t* a, const uint32_t* b) {
    asm volatile(
        "mma.sync.aligned.m16n8k16.row.col.f32.f16.f16.f32 "
        "{%0,%1,%2,%3}, {%4,%5,%6,%7}, {%8,%9}, {%0,%1,%2,%3};"
        : "+f"(c[0]), "+f"(c[1]), "+f"(c[2]), "+f"(c[3])
        : "r"(a[0]), "r"(a[1]), "r"(a[2]), "r"(a[3]), "r"(b[0]), "r"(b[1]));
}
__device__ __forceinline__ void cpa(uint32_t d, const void* s, int nbytes) {
    asm volatile("cp.async.cg.shared.global [%0], [%1], 16, %2;"
                 :: "r"(d), "l"(s), "r"(nbytes) : "memory");
}
#define CP_COMMIT() asm volatile("cp.async.commit_group;" ::: "memory")
#define CP_WAIT0()  asm volatile("cp.async.wait_group 0;" ::: "memory")
#define CP_WAIT1()  asm volatile("cp.async.wait_group 1;" ::: "memory")

// Conflict-free tile layout (verified): logical row x 16B-chunk -> swizzled offset.
__device__ __forceinline__ uint32_t tadr(int row, int ch) {
    return (uint32_t)((row >> 1) * 128 +
                      (((((row & 1) << 2) | ch) ^ ((row >> 1) & 7)) << 4));
}
__device__ __forceinline__ uint32_t pkh(__half a, __half b) {
    return (uint32_t)__half_as_ushort(a) | ((uint32_t)__half_as_ushort(b) << 16);
}

// ---------------- prepack: fp32 -> fp16 (weights + x) ------------------------
__global__ void w16_k(const float* __restrict__ in, __half* __restrict__ out, size_t n4)
{
    size_t i = (size_t)blockIdx.x * blockDim.x + threadIdx.x;
    size_t stride = (size_t)gridDim.x * blockDim.x;
    for (; i < n4; i += stride) {
        float4 v = ((const float4*)in)[i];
        uint2 o;
        o.x = pkh(__float2half(v.x), __float2half(v.y));
        o.y = pkh(__float2half(v.z), __float2half(v.w));
        ((uint2*)out)[i] = o;
    }
}

// ---------------- fused postproc: read once -> fp16, bf16 binT ---------------
// in fp32 [R, C]; h fp16 [R, C]; bT bf16 [C, R] binarized. C % 32 == 0.
__global__ void post_k(const float* __restrict__ in, __half* __restrict__ h,
                       __nv_bfloat16* __restrict__ bT, int R, int C)
{
    __shared__ float t[32][33];
    const int c0 = blockIdx.x * 32, r0 = blockIdx.y * 32;
    const int tx = threadIdx.x, ty = threadIdx.y;  // 32 x 8
#pragma unroll
    for (int i = 0; i < 4; i++) {
        int r = r0 + ty + i * 8, c = c0 + tx;
        float v = in[(size_t)r * C + c];
        t[ty + i * 8][tx] = v;
        h[(size_t)r * C + c] = __float2half(v);
    }
    __syncthreads();
    const __nv_bfloat16 one = __float2bfloat16(1.f);
    const __nv_bfloat16 zero = __float2bfloat16(0.f);
#pragma unroll
    for (int i = 0; i < 4; i++) {
        int oc = c0 + ty + i * 8;
        bT[(size_t)oc * R + r0 + tx] = (t[tx][ty + i * 8] > 0.f) ? one : zero;
    }
}

// ---------------- binarize + transpose (logits; ragged C, R = out stride) ----
__global__ void binT_k(const float* __restrict__ in, __nv_bfloat16* __restrict__ out,
                       int R, int C)
{
    __shared__ float t[32][33];
    const int c0 = blockIdx.x * 32, r0 = blockIdx.y * 32;
    const int tx = threadIdx.x, ty = threadIdx.y;  // 32 x 8
#pragma unroll
    for (int i = 0; i < 4; i++) {
        int r = r0 + ty + i * 8, c = c0 + tx;
        t[ty + i * 8][tx] = (c < C) ? in[(size_t)r * C + c] : 0.f;
    }
    __syncthreads();
    const __nv_bfloat16 one = __float2bfloat16(1.f);
    const __nv_bfloat16 zero = __float2bfloat16(0.f);
#pragma unroll
    for (int i = 0; i < 4; i++) {
        int oc = c0 + ty + i * 8;
        if (oc < C)
            out[(size_t)oc * R + r0 + tx] = (t[tx][ty + i * 8] > 0.f) ? one : zero;
    }
}

// ---------------- forward GEMM: single fp16 MMA, warp grid 4x2 ---------------
// C[M,N] = A @ B^T + bias [+relu]. A [M,K] fp16, B [N,K] fp16.
#define STAGES 3
#define FWD_STG 16384                 // A 8K | B 8K
#define FWD_SMEM (FWD_STG * STAGES)   // 48 KB
template <bool RELU>
__global__ void __launch_bounds__(256)
gemm_fwd(const __half* __restrict__ A, const __half* __restrict__ B,
         const float* __restrict__ bias, float* __restrict__ C,
         int M, int N, int K)
{
    extern __shared__ char smem[];
    const uint32_t sb = su32(smem);

    const int tid = threadIdx.x;
    const int lane = tid & 31, wid = tid >> 5;
    const int warp_m = wid & 3, warp_n = wid >> 2;     // 4 x 2 warps, 32x64 each
    const int m0 = blockIdx.y * 128, n0 = blockIdx.x * 128;

    float acc[2][8][4];
#pragma unroll
    for (int mi = 0; mi < 2; mi++)
#pragma unroll
        for (int ni = 0; ni < 8; ni++)
#pragma unroll
            for (int e = 0; e < 4; e++) acc[mi][ni][e] = 0.f;

    const int T = K >> 5;

    auto issue = [&](int t) {
        const uint32_t s = sb + (t % STAGES) * FWD_STG;
        const int k0 = t * 32;
#pragma unroll
        for (int j = 0; j < 2; j++) {
            const int cid = j * 256 + tid;
            const int row = cid >> 2, ch = cid & 3;
            const uint32_t soff = tadr(row, ch);
            cpa(s + soff, A + (size_t)(m0 + row) * K + k0 + ch * 8, 16);
            const int brow = n0 + row;
            const int ok = brow < N;
            cpa(s + 8192 + soff, B + (size_t)(ok ? brow : 0) * K + k0 + ch * 8, ok ? 16 : 0);
        }
        CP_COMMIT();
    };

    issue(0);
    issue(1);

    for (int t = 0; t < T; t++) {
        if (t == T - 1) CP_WAIT0(); else CP_WAIT1();
        __syncthreads();
        if (t + 2 < T) issue(t + 2);

        const uint32_t s = sb + (t % STAGES) * FWD_STG;
        const uint32_t sA = s, sB = s + 8192;

#pragma unroll
        for (int ks = 0; ks < 2; ks++) {
            uint32_t ah[2][4];
#pragma unroll
            for (int mi = 0; mi < 2; mi++) {
                const int row = warp_m * 32 + mi * 16 + (lane & 15);
                const int ch = ks * 2 + (lane >> 4);
                ldsm4(ah[mi], sA + tadr(row, ch));
            }
#pragma unroll
            for (int np = 0; np < 4; np++) {
                uint32_t bq[4];
                const int row = warp_n * 64 + (np * 2 + (lane >> 4)) * 8 + (lane & 7);
                const int ch = ks * 2 + ((lane >> 3) & 1);
                ldsm4(bq, sB + tadr(row, ch));
#pragma unroll
                for (int mi = 0; mi < 2; mi++) {
                    mma_f16(acc[mi][np * 2], ah[mi], bq);
                    mma_f16(acc[mi][np * 2 + 1], ah[mi], bq + 2);
                }
            }
        }
    }

#pragma unroll
    for (int mi = 0; mi < 2; mi++) {
        const int r0 = m0 + warp_m * 32 + mi * 16 + (lane >> 2);
#pragma unroll
        for (int ni = 0; ni < 8; ni++) {
            const int col = n0 + warp_n * 64 + ni * 8 + (lane & 3) * 2;
            if (col < N) {
                const float b0 = __ldg(bias + col), b1 = __ldg(bias + col + 1);
                float2 v0 = make_float2(acc[mi][ni][0] + b0, acc[mi][ni][1] + b1);
                float2 v1 = make_float2(acc[mi][ni][2] + b0, acc[mi][ni][3] + b1);
                if (RELU) {
                    v0.x = fmaxf(v0.x, 0.f); v0.y = fmaxf(v0.y, 0.f);
                    v1.x = fmaxf(v1.x, 0.f); v1.y = fmaxf(v1.y, 0.f);
                }
                *(float2*)(C + (size_t)r0 * N + col) = v0;
                *(float2*)(C + (size_t)(r0 + 8) * N + col) = v1;
            }
        }
    }
}

// ---------------- coact GEMM: bf16 0/1, exact; ldk = row stride --------------
// ACCUM: C += partial (exact integer partial sums -> fp32 add exact).
#define CO_STG 16384
#define CO_SMEM (CO_STG * STAGES)
template <bool ACCUM>
__global__ void __launch_bounds__(256)
gemm_co(const __nv_bfloat16* __restrict__ A, const __nv_bfloat16* __restrict__ B,
        float* __restrict__ C, int M, int N, int ldk, int K)
{
    extern __shared__ char smem[];
    const uint32_t sb = su32(smem);

    const int tid = threadIdx.x;
    const int lane = tid & 31, wid = tid >> 5;
    const int warp_m = wid & 1, warp_n = wid >> 1;     // 2 x 4, warp tile 64x32
    const int m0 = blockIdx.y * 128, n0 = blockIdx.x * 128;

    float acc[4][4][4];
#pragma unroll
    for (int mi = 0; mi < 4; mi++)
#pragma unroll
        for (int ni = 0; ni < 4; ni++)
#pragma unroll
            for (int e = 0; e < 4; e++) acc[mi][ni][e] = 0.f;

    const int T = K >> 5;

    auto issue = [&](int t) {
        const uint32_t s = sb + (t % STAGES) * CO_STG;
        const int k0 = t * 32;
#pragma unroll
        for (int j = 0; j < 2; j++) {
            const int cid = j * 256 + tid;
            const int row = cid >> 2, ch = cid & 3;
            const uint32_t soff = tadr(row, ch);
            cpa(s + soff, A + (size_t)(m0 + row) * ldk + k0 + ch * 8, 16);
            const int brow = n0 + row;
            const int ok = brow < N;
            cpa(s + 8192 + soff, B + (size_t)(ok ? brow : 0) * ldk + k0 + ch * 8, ok ? 16 : 0);
        }
        CP_COMMIT();
    };

    issue(0);
    issue(1);

    for (int t = 0; t < T; t++) {
        if (t == T - 1) CP_WAIT0(); else CP_WAIT1();
        __syncthreads();
        if (t + 2 < T) issue(t + 2);

        const uint32_t s = sb + (t % STAGES) * CO_STG;
        const uint32_t sA = s, sB = s + 8192;

#pragma unroll
        for (int ks = 0; ks < 2; ks++) {
            uint32_t a[4][4];
#pragma unroll
            for (int mi = 0; mi < 4; mi++) {
                const int row = warp_m * 64 + mi * 16 + (lane & 15);
                const int ch = ks * 2 + (lane >> 4);
                ldsm4(a[mi], sA + tadr(row, ch));
            }
#pragma unroll
            for (int np = 0; np < 2; np++) {
                uint32_t bq[4];
                const int row = warp_n * 32 + (np * 2 + (lane >> 4)) * 8 + (lane & 7);
                const int ch = ks * 2 + ((lane >> 3) & 1);
                ldsm4(bq, sB + tadr(row, ch));
#pragma unroll
                for (int mi = 0; mi < 4; mi++) {
                    mma_bf(acc[mi][np * 2], a[mi], bq);
                    mma_bf(acc[mi][np * 2 + 1], a[mi], bq + 2);
                }
            }
        }
    }

#pragma unroll
    for (int mi = 0; mi < 4; mi++) {
        const int r0 = m0 + warp_m * 64 + mi * 16 + (lane >> 2);
#pragma unroll
        for (int ni = 0; ni < 4; ni++) {
            const int col = n0 + warp_n * 32 + ni * 8 + (lane & 3) * 2;
            if (col < N) {
                float2 v0 = make_float2(acc[mi][ni][0], acc[mi][ni][1]);
                float2 v1 = make_float2(acc[mi][ni][2], acc[mi][ni][3]);
                if (ACCUM) {
                    float2 o0 = *(float2*)(C + (size_t)r0 * N + col);
                    float2 o1 = *(float2*)(C + (size_t)(r0 + 8) * N + col);
                    v0.x += o0.x; v0.y += o0.y; v1.x += o1.x; v1.y += o1.y;
                }
                *(float2*)(C + (size_t)r0 * N + col) = v0;
                *(float2*)(C + (size_t)(r0 + 8) * N + col) = v1;
            }
        }
    }
}

// ---------------- launch -----------------------------------------------------
extern "C" void kernel_launch(void* const* d_in, const int* in_sizes, int n_in,
                              void* d_out, int out_size)
{
    const float* x  = (const float*)d_in[0];
    const float* W1 = (const float*)d_in[1];
    const float* b1 = (const float*)d_in[2];
    const float* W2 = (const float*)d_in[3];
    const float* b2 = (const float*)d_in[4];
    const float* W3 = (const float*)d_in[5];
    const float* b3 = (const float*)d_in[6];

    float* out    = (float*)d_out;
    float* logits = out;
    float* coact0 = logits + (size_t)BATCH * N_CLS;
    float* coact1 = coact0 + (size_t)D_IN * H1;
    float* coact2 = coact1 + (size_t)H1 * H2;

    float *a1, *a2;
    __half *xh, *a1h, *a2h, *w1h, *w2h, *w3h;
    __nv_bfloat16 *xbT, *a1bT, *a2bT, *lbT;
    cudaGetSymbolAddress((void**)&a1, g_a1);
    cudaGetSymbolAddress((void**)&a2, g_a2);
    cudaGetSymbolAddress((void**)&xh, g_xh);
    cudaGetSymbolAddress((void**)&a1h, g_a1h);
    cudaGetSymbolAddress((void**)&a2h, g_a2h);
    cudaGetSymbolAddress((void**)&w1h, g_w1h);
    cudaGetSymbolAddress((void**)&w2h, g_w2h);
    cudaGetSymbolAddress((void**)&w3h, g_w3h);
    cudaGetSymbolAddress((void**)&xbT, g_xbT);   cudaGetSymbolAddress((void**)&a1bT, g_a1bT);
    cudaGetSymbolAddress((void**)&a2bT, g_a2bT); cudaGetSymbolAddress((void**)&lbT, g_lbT);

    static bool s_init = false;
    static cudaStream_t s_side;
    static cudaEvent_t evFork, evW23, evPrep1, evPrep2, evC0, evC1, evL3a, evC2a;
    if (!s_init) {
        cudaStreamCreateWithFlags(&s_side, cudaStreamNonBlocking);
        cudaEventCreateWithFlags(&evFork, cudaEventDisableTiming);
        cudaEventCreateWithFlags(&evW23, cudaEventDisableTiming);
        cudaEventCreateWithFlags(&evPrep1, cudaEventDisableTiming);
        cudaEventCreateWithFlags(&evPrep2, cudaEventDisableTiming);
        cudaEventCreateWithFlags(&evC0, cudaEventDisableTiming);
        cudaEventCreateWithFlags(&evC1, cudaEventDisableTiming);
        cudaEventCreateWithFlags(&evL3a, cudaEventDisableTiming);
        cudaEventCreateWithFlags(&evC2a, cudaEventDisableTiming);
        cudaFuncSetAttribute(gemm_fwd<true>, cudaFuncAttributeMaxDynamicSharedMemorySize, FWD_SMEM);
        cudaFuncSetAttribute(gemm_fwd<false>, cudaFuncAttributeMaxDynamicSharedMemorySize, FWD_SMEM);
        cudaFuncSetAttribute(gemm_co<false>, cudaFuncAttributeMaxDynamicSharedMemorySize, CO_SMEM);
        cudaFuncSetAttribute(gemm_co<true>, cudaFuncAttributeMaxDynamicSharedMemorySize, CO_SMEM);
        s_init = true;
    }

    const dim3 blk(256);
    const dim3 tb(32, 8);

    // capture-legal fork
    cudaEventRecord(evFork, 0);
    cudaStreamWaitEvent(s_side, evFork, 0);

    // main: prepack for fwd1 (x fp16 + xbT in one pass, W1 fp16)
    post_k<<<dim3(D_IN / 32, BATCH / 32), tb>>>(x, xh, xbT, BATCH, D_IN);
    w16_k<<<1024, 256>>>(W1, w1h, (size_t)H1 * D_IN / 4);

    // side: W2/W3 fp16 overlap fwd1
    w16_k<<<1024, 256, 0, s_side>>>(W2, w2h, (size_t)H2 * H1 / 4);
    w16_k<<<1024, 256, 0, s_side>>>(W3, w3h, (size_t)N_CLS * H2 / 4);
    cudaEventRecord(evW23, s_side);

    // fwd1 + postproc
    gemm_fwd<true><<<dim3(H1 / 128, BATCH / 128), blk, FWD_SMEM>>>(
        xh, w1h, b1, a1, BATCH, H1, D_IN);
    post_k<<<dim3(H1 / 32, BATCH / 32), tb>>>(a1, a1h, a1bT, BATCH, H1);
    cudaEventRecord(evPrep1, 0);

    // side: coact0 overlaps fwd2
    cudaStreamWaitEvent(s_side, evPrep1, 0);
    gemm_co<false><<<dim3(H1 / 128, D_IN / 128), blk, CO_SMEM, s_side>>>(
        xbT, a1bT, coact0, D_IN, H1, BATCH, BATCH);
    cudaEventRecord(evC0, s_side);

    // fwd2 + postproc
    cudaStreamWaitEvent(0, evW23, 0);
    gemm_fwd<true><<<dim3(H2 / 128, BATCH / 128), blk, FWD_SMEM>>>(
        a1h, w2h, b2, a2, BATCH, H2, H1);
    post_k<<<dim3(H2 / 32, BATCH / 32), tb>>>(a2, a2h, a2bT, BATCH, H2);
    cudaEventRecord(evPrep2, 0);

    // side: coact1 overlaps fwd3
    cudaStreamWaitEvent(s_side, evPrep2, 0);
    gemm_co<false><<<dim3(H2 / 128, H1 / 128), blk, CO_SMEM, s_side>>>(
        a1bT, a2bT, coact1, H1, H2, BATCH, BATCH);
    cudaEventRecord(evC1, s_side);

    // fwd3a: logits rows [0, HALF_B)
    gemm_fwd<false><<<dim3((N_CLS + 127) / 128, HALF_B / 128), blk, FWD_SMEM>>>(
        a2h, w3h, b3, logits, HALF_B, N_CLS, H2);
    cudaEventRecord(evL3a, 0);

    // side: binT(logits a) + coact2a (init) overlap fwd3b
    cudaStreamWaitEvent(s_side, evL3a, 0);
    binT_k<<<dim3((N_CLS + 31) / 32, HALF_B / 32), tb, 0, s_side>>>(
        logits, lbT, BATCH, N_CLS);
    gemm_co<false><<<dim3((N_CLS + 127) / 128, H2 / 128), blk, CO_SMEM, s_side>>>(
        a2bT, lbT, coact2, H2, N_CLS, BATCH, HALF_B);
    cudaEventRecord(evC2a, s_side);

    // fwd3b: logits rows [HALF_B, BATCH)
    gemm_fwd<false><<<dim3((N_CLS + 127) / 128, HALF_B / 128), blk, FWD_SMEM>>>(
        a2h + (size_t)HALF_B * H2, w3h, b3,
        logits + (size_t)HALF_B * N_CLS, HALF_B, N_CLS, H2);
    binT_k<<<dim3((N_CLS + 31) / 32, HALF_B / 32), tb>>>(
        logits + (size_t)HALF_B * N_CLS, lbT + HALF_B, BATCH, N_CLS);

    // coact2b: accumulate second K-half (waits coact2a)
    cudaStreamWaitEvent(0, evC2a, 0);
    gemm_co<true><<<dim3((N_CLS + 127) / 128, H2 / 128), blk, CO_SMEM>>>(
        a2bT + HALF_B, lbT + HALF_B, coact2, H2, N_CLS, BATCH, HALF_B);

    // join side stream
    cudaStreamWaitEvent(0, evC0, 0);
    cudaStreamWaitEvent(0, evC1, 0);
}

// round 16
// speedup vs baseline: 2.1055x; 1.0077x over previous
#include <cuda_runtime.h>
#include <cuda_bf16.h>
#include <cuda_fp16.h>
#include <stdint.h>

#define BATCH 8192
#define D_IN  1024
#define H1    2048
#define H2    2048
#define N_CLS 1000
#define HALF_B 4096
#define FP8_ONE 0x38  // e4m3 1.0

// ---------------- scratch (device globals; no allocations allowed) ----------
__device__ float g_a1[(size_t)BATCH * H1];
__device__ float g_a2[(size_t)BATCH * H2];
__device__ __align__(256) __half g_xh[(size_t)BATCH * D_IN];
__device__ __align__(256) __half g_a1h[(size_t)BATCH * H1];
__device__ __align__(256) __half g_a2h[(size_t)BATCH * H2];
__device__ __align__(256) __half g_w1h[(size_t)H1 * D_IN];
__device__ __align__(256) __half g_w2h[(size_t)H2 * H1];
__device__ __align__(256) __half g_w3h[(size_t)N_CLS * H2];
__device__ __align__(256) uint8_t g_xbT[(size_t)D_IN * BATCH];
__device__ __align__(256) uint8_t g_a1bT[(size_t)H1 * BATCH];
__device__ __align__(256) uint8_t g_a2bT[(size_t)H2 * BATCH];
__device__ __align__(256) uint8_t g_lbT[(size_t)N_CLS * BATCH];

// ---------------- PTX helpers ------------------------------------------------
__device__ __forceinline__ uint32_t su32(const void* p) {
    uint32_t a;
    asm("{ .reg .u64 t; cvta.to.shared.u64 t, %1; cvt.u32.u64 %0, t; }" : "=r"(a) : "l"(p));
    return a;
}
__device__ __forceinline__ void ldsm4(uint32_t* r, uint32_t a) {
    asm volatile("ldmatrix.sync.aligned.m8n8.x4.shared.b16 {%0,%1,%2,%3}, [%4];"
                 : "=r"(r[0]), "=r"(r[1]), "=r"(r[2]), "=r"(r[3]) : "r"(a));
}
__device__ __forceinline__ void mma_f16(float* c, const uint32_t* a, const uint32_t* b) {
    asm volatile(
        "mma.sync.aligned.m16n8k16.row.col.f32.f16.f16.f32 "
        "{%0,%1,%2,%3}, {%4,%5,%6,%7}, {%8,%9}, {%0,%1,%2,%3};"
        : "+f"(c[0]), "+f"(c[1]), "+f"(c[2]), "+f"(c[3])
        : "r"(a[0]), "r"(a[1]), "r"(a[2]), "r"(a[3]), "r"(b[0]), "r"(b[1]));
}
__device__ __forceinline__ void mma_e4m3(float* c, const uint32_t* a, const uint32_t* b) {
    asm volatile(
        "mma.sync.aligned.m16n8k32.row.col.f32.e4m3.e4m3.f32 "
        "{%0,%1,%2,%3}, {%4,%5,%6,%7}, {%8,%9}, {%0,%1,%2,%3};"
        : "+f"(c[0]), "+f"(c[1]), "+f"(c[2]), "+f"(c[3])
        : "r"(a[0]), "r"(a[1]), "r"(a[2]), "r"(a[3]), "r"(b[0]), "r"(b[1]));
}
__device__ __forceinline__ void cpa(uint32_t d, const void* s, int nbytes) {
    asm volatile("cp.async.cg.shared.global [%0], [%1], 16, %2;"
                 :: "r"(d), "l"(s), "r"(nbytes) : "memory");
}
#define CP_COMMIT() asm volatile("cp.async.commit_group;" ::: "memory")
#define CP_WAIT0()  asm volatile("cp.async.wait_group 0;" ::: "memory")
#define CP_WAIT1()  asm volatile("cp.async.wait_group 1;" ::: "memory")

// Conflict-free tile layout (verified): logical row x 16B-chunk -> swizzled offset.
__device__ __forceinline__ uint32_t tadr(int row, int ch) {
    return (uint32_t)((row >> 1) * 128 +
                      (((((row & 1) << 2) | ch) ^ ((row >> 1) & 7)) << 4));
}
__device__ __forceinline__ uint32_t pkh(__half a, __half b) {
    return (uint32_t)__half_as_ushort(a) | ((uint32_t)__half_as_ushort(b) << 16);
}

// ---------------- prepack: fp32 -> fp16 (weights) ----------------------------
__global__ void w16_k(const float* __restrict__ in, __half* __restrict__ out, size_t n4)
{
    size_t i = (size_t)blockIdx.x * blockDim.x + threadIdx.x;
    size_t stride = (size_t)gridDim.x * blockDim.x;
    for (; i < n4; i += stride) {
        float4 v = ((const float4*)in)[i];
        uint2 o;
        o.x = pkh(__float2half(v.x), __float2half(v.y));
        o.y = pkh(__float2half(v.z), __float2half(v.w));
        ((uint2*)out)[i] = o;
    }
}

// ---------------- fused postproc: read once -> fp16, fp8 binT ----------------
__global__ void post_k(const float* __restrict__ in, __half* __restrict__ h,
                       uint8_t* __restrict__ bT, int R, int C)
{
    __shared__ float t[32][33];
    const int c0 = blockIdx.x * 32, r0 = blockIdx.y * 32;
    const int tx = threadIdx.x, ty = threadIdx.y;  // 32 x 8
#pragma unroll
    for (int i = 0; i < 4; i++) {
        int r = r0 + ty + i * 8, c = c0 + tx;
        float v = in[(size_t)r * C + c];
        t[ty + i * 8][tx] = v;
        h[(size_t)r * C + c] = __float2half(v);
    }
    __syncthreads();
#pragma unroll
    for (int i = 0; i < 4; i++) {
        int oc = c0 + ty + i * 8;
        bT[(size_t)oc * R + r0 + tx] = (t[tx][ty + i * 8] > 0.f) ? FP8_ONE : 0;
    }
}

// ---------------- binarize + transpose (logits; ragged C, R = out stride) ----
__global__ void binT_k(const float* __restrict__ in, uint8_t* __restrict__ out,
                       int R, int C)
{
    __shared__ float t[32][33];
    const int c0 = blockIdx.x * 32, r0 = blockIdx.y * 32;
    const int tx = threadIdx.x, ty = threadIdx.y;  // 32 x 8
#pragma unroll
    for (int i = 0; i < 4; i++) {
        int r = r0 + ty + i * 8, c = c0 + tx;
        t[ty + i * 8][tx] = (c < C) ? in[(size_t)r * C + c] : 0.f;
    }
    __syncthreads();
#pragma unroll
    for (int i = 0; i < 4; i++) {
        int oc = c0 + ty + i * 8;
        if (oc < C)
            out[(size_t)oc * R + r0 + tx] = (t[tx][ty + i * 8] > 0.f) ? FP8_ONE : 0;
    }
}

// ---------------- forward GEMM: single fp16 MMA, warp grid 4x2 (R14) ---------
#define STAGES 3
#define FWD_STG 16384
#define FWD_SMEM (FWD_STG * STAGES)
template <bool RELU>
__global__ void __launch_bounds__(256)
gemm_fwd(const __half* __restrict__ A, const __half* __restrict__ B,
         const float* __restrict__ bias, float* __restrict__ C,
         int M, int N, int K)
{
    extern __shared__ char smem[];
    const uint32_t sb = su32(smem);

    const int tid = threadIdx.x;
    const int lane = tid & 31, wid = tid >> 5;
    const int warp_m = wid & 3, warp_n = wid >> 2;     // 4 x 2 warps, 32x64 each
    const int m0 = blockIdx.y * 128, n0 = blockIdx.x * 128;

    float acc[2][8][4];
#pragma unroll
    for (int mi = 0; mi < 2; mi++)
#pragma unroll
        for (int ni = 0; ni < 8; ni++)
#pragma unroll
            for (int e = 0; e < 4; e++) acc[mi][ni][e] = 0.f;

    const int T = K >> 5;

    auto issue = [&](int t) {
        const uint32_t s = sb + (t % STAGES) * FWD_STG;
        const int k0 = t * 32;
#pragma unroll
        for (int j = 0; j < 2; j++) {
            const int cid = j * 256 + tid;
            const int row = cid >> 2, ch = cid & 3;
            const uint32_t soff = tadr(row, ch);
            cpa(s + soff, A + (size_t)(m0 + row) * K + k0 + ch * 8, 16);
            const int brow = n0 + row;
            const int ok = brow < N;
            cpa(s + 8192 + soff, B + (size_t)(ok ? brow : 0) * K + k0 + ch * 8, ok ? 16 : 0);
        }
        CP_COMMIT();
    };

    issue(0);
    issue(1);

    for (int t = 0; t < T; t++) {
        if (t == T - 1) CP_WAIT0(); else CP_WAIT1();
        __syncthreads();
        if (t + 2 < T) issue(t + 2);

        const uint32_t s = sb + (t % STAGES) * FWD_STG;
        const uint32_t sA = s, sB = s + 8192;

#pragma unroll
        for (int ks = 0; ks < 2; ks++) {
            uint32_t ah[2][4];
#pragma unroll
            for (int mi = 0; mi < 2; mi++) {
                const int row = warp_m * 32 + mi * 16 + (lane & 15);
                const int ch = ks * 2 + (lane >> 4);
                ldsm4(ah[mi], sA + tadr(row, ch));
            }
#pragma unroll
            for (int np = 0; np < 4; np++) {
                uint32_t bq[4];
                const int row = warp_n * 64 + (np * 2 + (lane >> 4)) * 8 + (lane & 7);
                const int ch = ks * 2 + ((lane >> 3) & 1);
                ldsm4(bq, sB + tadr(row, ch));
#pragma unroll
                for (int mi = 0; mi < 2; mi++) {
                    mma_f16(acc[mi][np * 2], ah[mi], bq);
                    mma_f16(acc[mi][np * 2 + 1], ah[mi], bq + 2);
                }
            }
        }
    }

#pragma unroll
    for (int mi = 0; mi < 2; mi++) {
        const int r0 = m0 + warp_m * 32 + mi * 16 + (lane >> 2);
#pragma unroll
        for (int ni = 0; ni < 8; ni++) {
            const int col = n0 + warp_n * 64 + ni * 8 + (lane & 3) * 2;
            if (col < N) {
                const float b0 = __ldg(bias + col), b1 = __ldg(bias + col + 1);
                float2 v0 = make_float2(acc[mi][ni][0] + b0, acc[mi][ni][1] + b1);
                float2 v1 = make_float2(acc[mi][ni][2] + b0, acc[mi][ni][3] + b1);
                if (RELU) {
                    v0.x = fmaxf(v0.x, 0.f); v0.y = fmaxf(v0.y, 0.f);
                    v1.x = fmaxf(v1.x, 0.f); v1.y = fmaxf(v1.y, 0.f);
                }
                *(float2*)(C + (size_t)r0 * N + col) = v0;
                *(float2*)(C + (size_t)(r0 + 8) * N + col) = v1;
            }
        }
    }
}

// ---------------- coact GEMM: fp8 e4m3 0/1, exact; K-chunk 64B ---------------
// C[m,n] = sum_k A[m,k]*B[n,k]; A [M,ldk] u8, B [N,ldk] u8; fp32 acc exact.
// Fragment indexing identical to the numerically-verified R6 s8 engine.
#define CO_STG 16384                  // A 8K | B 8K (128 rows x 64B each)
#define CO_SMEM (CO_STG * STAGES)
template <bool ACCUM>
__global__ void __launch_bounds__(256)
gemm_co(const uint8_t* __restrict__ A, const uint8_t* __restrict__ B,
        float* __restrict__ C, int M, int N, int ldk, int K)
{
    extern __shared__ char smem[];
    const uint32_t sb = su32(smem);

    const int tid = threadIdx.x;
    const int lane = tid & 31, wid = tid >> 5;
    const int warp_m = wid & 1, warp_n = wid >> 1;     // 2 x 4, warp tile 64x32
    const int m0 = blockIdx.y * 128, n0 = blockIdx.x * 128;

    float acc[4][4][4];
#pragma unroll
    for (int mi = 0; mi < 4; mi++)
#pragma unroll
        for (int ni = 0; ni < 4; ni++)
#pragma unroll
            for (int e = 0; e < 4; e++) acc[mi][ni][e] = 0.f;

    const int T = K >> 6;   // 64-byte k-chunks

    auto issue = [&](int t) {
        const uint32_t s = sb + (t % STAGES) * CO_STG;
        const int k0 = t * 64;
#pragma unroll
        for (int j = 0; j < 2; j++) {
            const int cid = j * 256 + tid;
            const int row = cid >> 2, ch = cid & 3;
            const uint32_t soff = tadr(row, ch);
            cpa(s + soff, A + (size_t)(m0 + row) * ldk + k0 + ch * 16, 16);
            const int brow = n0 + row;
            const int ok = brow < N;
            cpa(s + 8192 + soff, B + (size_t)(ok ? brow : 0) * ldk + k0 + ch * 16, ok ? 16 : 0);
        }
        CP_COMMIT();
    };

    issue(0);
    issue(1);

    for (int t = 0; t < T; t++) {
        if (t == T - 1) CP_WAIT0(); else CP_WAIT1();
        __syncthreads();
        if (t + 2 < T) issue(t + 2);

        const uint32_t s = sb + (t % STAGES) * CO_STG;
        const uint32_t sA = s, sB = s + 8192;

        uint32_t bq[4][4];
#pragma unroll
        for (int ni = 0; ni < 4; ni++) {
            const int row = warp_n * 32 + ni * 8 + (lane & 7);
            const int ch = lane >> 3;
            ldsm4(bq[ni], sB + tadr(row, ch));
        }
#pragma unroll
        for (int ks = 0; ks < 2; ks++) {
            uint32_t a[4][4];
#pragma unroll
            for (int mi = 0; mi < 4; mi++) {
                const int row = warp_m * 64 + mi * 16 + (lane & 15);
                const int ch = ks * 2 + (lane >> 4);
                ldsm4(a[mi], sA + tadr(row, ch));
            }
#pragma unroll
            for (int mi = 0; mi < 4; mi++)
#pragma unroll
                for (int ni = 0; ni < 4; ni++)
                    mma_e4m3(acc[mi][ni], a[mi], &bq[ni][2 * ks]);
        }
    }

#pragma unroll
    for (int mi = 0; mi < 4; mi++) {
        const int r0 = m0 + warp_m * 64 + mi * 16 + (lane >> 2);
#pragma unroll
        for (int ni = 0; ni < 4; ni++) {
            const int col = n0 + warp_n * 32 + ni * 8 + (lane & 3) * 2;
            if (col < N) {
                float2 v0 = make_float2(acc[mi][ni][0], acc[mi][ni][1]);
                float2 v1 = make_float2(acc[mi][ni][2], acc[mi][ni][3]);
                if (ACCUM) {
                    float2 o0 = *(float2*)(C + (size_t)r0 * N + col);
                    float2 o1 = *(float2*)(C + (size_t)(r0 + 8) * N + col);
                    v0.x += o0.x; v0.y += o0.y; v1.x += o1.x; v1.y += o1.y;
                }
                *(float2*)(C + (size_t)r0 * N + col) = v0;
                *(float2*)(C + (size_t)(r0 + 8) * N + col) = v1;
            }
        }
    }
}

// ---------------- launch -----------------------------------------------------
extern "C" void kernel_launch(void* const* d_in, const int* in_sizes, int n_in,
                              void* d_out, int out_size)
{
    const float* x  = (const float*)d_in[0];
    const float* W1 = (const float*)d_in[1];
    const float* b1 = (const float*)d_in[2];
    const float* W2 = (const float*)d_in[3];
    const float* b2 = (const float*)d_in[4];
    const float* W3 = (const float*)d_in[5];
    const float* b3 = (const float*)d_in[6];

    float* out    = (float*)d_out;
    float* logits = out;
    float* coact0 = logits + (size_t)BATCH * N_CLS;
    float* coact1 = coact0 + (size_t)D_IN * H1;
    float* coact2 = coact1 + (size_t)H1 * H2;

    float *a1, *a2;
    __half *xh, *a1h, *a2h, *w1h, *w2h, *w3h;
    uint8_t *xbT, *a1bT, *a2bT, *lbT;
    cudaGetSymbolAddress((void**)&a1, g_a1);
    cudaGetSymbolAddress((void**)&a2, g_a2);
    cudaGetSymbolAddress((void**)&xh, g_xh);
    cudaGetSymbolAddress((void**)&a1h, g_a1h);
    cudaGetSymbolAddress((void**)&a2h, g_a2h);
    cudaGetSymbolAddress((void**)&w1h, g_w1h);
    cudaGetSymbolAddress((void**)&w2h, g_w2h);
    cudaGetSymbolAddress((void**)&w3h, g_w3h);
    cudaGetSymbolAddress((void**)&xbT, g_xbT);   cudaGetSymbolAddress((void**)&a1bT, g_a1bT);
    cudaGetSymbolAddress((void**)&a2bT, g_a2bT); cudaGetSymbolAddress((void**)&lbT, g_lbT);

    static bool s_init = false;
    static cudaStream_t s_side;
    static cudaEvent_t evFork, evW23, evPrep1, evPrep2, evC0, evC1, evL3a, evC2a;
    if (!s_init) {
        cudaStreamCreateWithFlags(&s_side, cudaStreamNonBlocking);
        cudaEventCreateWithFlags(&evFork, cudaEventDisableTiming);
        cudaEventCreateWithFlags(&evW23, cudaEventDisableTiming);
        cudaEventCreateWithFlags(&evPrep1, cudaEventDisableTiming);
        cudaEventCreateWithFlags(&evPrep2, cudaEventDisableTiming);
        cudaEventCreateWithFlags(&evC0, cudaEventDisableTiming);
        cudaEventCreateWithFlags(&evC1, cudaEventDisableTiming);
        cudaEventCreateWithFlags(&evL3a, cudaEventDisableTiming);
        cudaEventCreateWithFlags(&evC2a, cudaEventDisableTiming);
        cudaFuncSetAttribute(gemm_fwd<true>, cudaFuncAttributeMaxDynamicSharedMemorySize, FWD_SMEM);
        cudaFuncSetAttribute(gemm_fwd<false>, cudaFuncAttributeMaxDynamicSharedMemorySize, FWD_SMEM);
        cudaFuncSetAttribute(gemm_co<false>, cudaFuncAttributeMaxDynamicSharedMemorySize, CO_SMEM);
        cudaFuncSetAttribute(gemm_co<true>, cudaFuncAttributeMaxDynamicSharedMemorySize, CO_SMEM);
        s_init = true;
    }

    const dim3 blk(256);
    const dim3 tb(32, 8);

    // capture-legal fork
    cudaEventRecord(evFork, 0);
    cudaStreamWaitEvent(s_side, evFork, 0);

    // main: prepack for fwd1
    post_k<<<dim3(D_IN / 32, BATCH / 32), tb>>>(x, xh, xbT, BATCH, D_IN);
    w16_k<<<1024, 256>>>(W1, w1h, (size_t)H1 * D_IN / 4);

    // side: W2/W3 fp16 overlap fwd1
    w16_k<<<1024, 256, 0, s_side>>>(W2, w2h, (size_t)H2 * H1 / 4);
    w16_k<<<1024, 256, 0, s_side>>>(W3, w3h, (size_t)N_CLS * H2 / 4);
    cudaEventRecord(evW23, s_side);

    // fwd1 + postproc
    gemm_fwd<true><<<dim3(H1 / 128, BATCH / 128), blk, FWD_SMEM>>>(
        xh, w1h, b1, a1, BATCH, H1, D_IN);
    post_k<<<dim3(H1 / 32, BATCH / 32), tb>>>(a1, a1h, a1bT, BATCH, H1);
    cudaEventRecord(evPrep1, 0);

    // side: coact0 overlaps fwd2
    cudaStreamWaitEvent(s_side, evPrep1, 0);
    gemm_co<false><<<dim3(H1 / 128, D_IN / 128), blk, CO_SMEM, s_side>>>(
        xbT, a1bT, coact0, D_IN, H1, BATCH, BATCH);
    cudaEventRecord(evC0, s_side);

    // fwd2 + postproc
    cudaStreamWaitEvent(0, evW23, 0);
    gemm_fwd<true><<<dim3(H2 / 128, BATCH / 128), blk, FWD_SMEM>>>(
        a1h, w2h, b2, a2, BATCH, H2, H1);
    post_k<<<dim3(H2 / 32, BATCH / 32), tb>>>(a2, a2h, a2bT, BATCH, H2);
    cudaEventRecord(evPrep2, 0);

    // side: coact1 overlaps fwd3
    cudaStreamWaitEvent(s_side, evPrep2, 0);
    gemm_co<false><<<dim3(H2 / 128, H1 / 128), blk, CO_SMEM, s_side>>>(
        a1bT, a2bT, coact1, H1, H2, BATCH, BATCH);
    cudaEventRecord(evC1, s_side);

    // fwd3a: logits rows [0, HALF_B)
    gemm_fwd<false><<<dim3((N_CLS + 127) / 128, HALF_B / 128), blk, FWD_SMEM>>>(
        a2h, w3h, b3, logits, HALF_B, N_CLS, H2);
    cudaEventRecord(evL3a, 0);

    // side: binT(logits a) + coact2a overlap fwd3b
    cudaStreamWaitEvent(s_side, evL3a, 0);
    binT_k<<<dim3((N_CLS + 31) / 32, HALF_B / 32), tb, 0, s_side>>>(
        logits, lbT, BATCH, N_CLS);
    gemm_co<false><<<dim3((N_CLS + 127) / 128, H2 / 128), blk, CO_SMEM, s_side>>>(
        a2bT, lbT, coact2, H2, N_CLS, BATCH, HALF_B);
    cudaEventRecord(evC2a, s_side);

    // fwd3b
    gemm_fwd<false><<<dim3((N_CLS + 127) / 128, HALF_B / 128), blk, FWD_SMEM>>>(
        a2h + (size_t)HALF_B * H2, w3h, b3,
        logits + (size_t)HALF_B * N_CLS, HALF_B, N_CLS, H2);
    binT_k<<<dim3((N_CLS + 31) / 32, HALF_B / 32), tb>>>(
        logits + (size_t)HALF_B * N_CLS, lbT + HALF_B, BATCH, N_CLS);

    // coact2b: accumulate second K-half
    cudaStreamWaitEvent(0, evC2a, 0);
    gemm_co<true><<<dim3((N_CLS + 127) / 128, H2 / 128), blk, CO_SMEM>>>(
        a2bT + HALF_B, lbT + HALF_B, coact2, H2, N_CLS, BATCH, HALF_B);

    // join side stream
    cudaStreamWaitEvent(0, evC0, 0);
    cudaStreamWaitEvent(0, evC1, 0);
}

// round 17
// speedup vs baseline: 2.1513x; 1.0218x over previous
#include <cuda_runtime.h>
#include <cuda_bf16.h>
#include <cuda_fp16.h>
#include <stdint.h>

#define BATCH 8192
#define D_IN  1024
#define H1    2048
#define H2    2048
#define N_CLS 1000
#define HALF_B 4096
#define FP8_ONE 0x38  // e4m3 1.0

// ---------------- scratch (device globals; no allocations allowed) ----------
__device__ __align__(256) __half g_xh[(size_t)BATCH * D_IN];
__device__ __align__(256) __half g_a1h[(size_t)BATCH * H1];
__device__ __align__(256) __half g_a2h[(size_t)BATCH * H2];
__device__ __align__(256) __half g_w1h[(size_t)H1 * D_IN];
__device__ __align__(256) __half g_w2h[(size_t)H2 * H1];
__device__ __align__(256) __half g_w3h[(size_t)N_CLS * H2];
__device__ __align__(256) uint8_t g_xbT[(size_t)D_IN * BATCH];
__device__ __align__(256) uint8_t g_a1bT[(size_t)H1 * BATCH];
__device__ __align__(256) uint8_t g_a2bT[(size_t)H2 * BATCH];
__device__ __align__(256) uint8_t g_lbT[(size_t)N_CLS * BATCH];

// ---------------- PTX helpers ------------------------------------------------
__device__ __forceinline__ uint32_t su32(const void* p) {
    uint32_t a;
    asm("{ .reg .u64 t; cvta.to.shared.u64 t, %1; cvt.u32.u64 %0, t; }" : "=r"(a) : "l"(p));
    return a;
}
__device__ __forceinline__ void ldsm4(uint32_t* r, uint32_t a) {
    asm volatile("ldmatrix.sync.aligned.m8n8.x4.shared.b16 {%0,%1,%2,%3}, [%4];"
                 : "=r"(r[0]), "=r"(r[1]), "=r"(r[2]), "=r"(r[3]) : "r"(a));
}
__device__ __forceinline__ void mma_f16(float* c, const uint32_t* a, const uint32_t* b) {
    asm volatile(
        "mma.sync.aligned.m16n8k16.row.col.f32.f16.f16.f32 "
        "{%0,%1,%2,%3}, {%4,%5,%6,%7}, {%8,%9}, {%0,%1,%2,%3};"
        : "+f"(c[0]), "+f"(c[1]), "+f"(c[2]), "+f"(c[3])
        : "r"(a[0]), "r"(a[1]), "r"(a[2]), "r"(a[3]), "r"(b[0]), "r"(b[1]));
}
__device__ __forceinline__ void mma_e4m3(float* c, const uint32_t* a, const uint32_t* b) {
    asm volatile(
        "mma.sync.aligned.m16n8k32.row.col.f32.e4m3.e4m3.f32 "
        "{%0,%1,%2,%3}, {%4,%5,%6,%7}, {%8,%9}, {%0,%1,%2,%3};"
        : "+f"(c[0]), "+f"(c[1]), "+f"(c[2]), "+f"(c[3])
        : "r"(a[0]), "r"(a[1]), "r"(a[2]), "r"(a[3]), "r"(b[0]), "r"(b[1]));
}
__device__ __forceinline__ void cpa(uint32_t d, const void* s, int nbytes) {
    asm volatile("cp.async.cg.shared.global [%0], [%1], 16, %2;"
                 :: "r"(d), "l"(s), "r"(nbytes) : "memory");
}
#define CP_COMMIT() asm volatile("cp.async.commit_group;" ::: "memory")
#define CP_WAIT0()  asm volatile("cp.async.wait_group 0;" ::: "memory")
#define CP_WAIT1()  asm volatile("cp.async.wait_group 1;" ::: "memory")

// Conflict-free tile layout (verified): logical row x 16B-chunk -> swizzled offset.
__device__ __forceinline__ uint32_t tadr(int row, int ch) {
    return (uint32_t)((row >> 1) * 128 +
                      (((((row & 1) << 2) | ch) ^ ((row >> 1) & 7)) << 4));
}
__device__ __forceinline__ uint32_t pkh(__half a, __half b) {
    return (uint32_t)__half_as_ushort(a) | ((uint32_t)__half_as_ushort(b) << 16);
}

// ---------------- prepack: fp32 -> fp16 (weights) ----------------------------
__global__ void w16_k(const float* __restrict__ in, __half* __restrict__ out, size_t n4)
{
    size_t i = (size_t)blockIdx.x * blockDim.x + threadIdx.x;
    size_t stride = (size_t)gridDim.x * blockDim.x;
    for (; i < n4; i += stride) {
        float4 v = ((const float4*)in)[i];
        uint2 o;
        o.x = pkh(__float2half(v.x), __float2half(v.y));
        o.y = pkh(__float2half(v.z), __float2half(v.w));
        ((uint2*)out)[i] = o;
    }
}

// ---------------- x prepack: fp32 -> fp16 + fp8 binT -------------------------
__global__ void post_k(const float* __restrict__ in, __half* __restrict__ h,
                       uint8_t* __restrict__ bT, int R, int C)
{
    __shared__ float t[32][33];
    const int c0 = blockIdx.x * 32, r0 = blockIdx.y * 32;
    const int tx = threadIdx.x, ty = threadIdx.y;  // 32 x 8
#pragma unroll
    for (int i = 0; i < 4; i++) {
        int r = r0 + ty + i * 8, c = c0 + tx;
        float v = in[(size_t)r * C + c];
        t[ty + i * 8][tx] = v;
        h[(size_t)r * C + c] = __float2half(v);
    }
    __syncthreads();
#pragma unroll
    for (int i = 0; i < 4; i++) {
        int oc = c0 + ty + i * 8;
        bT[(size_t)oc * R + r0 + tx] = (t[tx][ty + i * 8] > 0.f) ? FP8_ONE : 0;
    }
}

// ---------------- act binT: fp16 [R,C] -> fp8 0/1 [C,R] ----------------------
__global__ void binT16_k(const __half* __restrict__ in, uint8_t* __restrict__ out,
                         int R, int C)
{
    __shared__ __half t[32][34];
    const int c0 = blockIdx.x * 32, r0 = blockIdx.y * 32;
    const int tx = threadIdx.x, ty = threadIdx.y;  // 32 x 8
#pragma unroll
    for (int i = 0; i < 4; i++) {
        int r = r0 + ty + i * 8, c = c0 + tx;
        t[ty + i * 8][tx] = in[(size_t)r * C + c];
    }
    __syncthreads();
#pragma unroll
    for (int i = 0; i < 4; i++) {
        int oc = c0 + ty + i * 8;
        out[(size_t)oc * R + r0 + tx] =
            (__half2float(t[tx][ty + i * 8]) > 0.f) ? FP8_ONE : 0;
    }
}

// ---------------- logits binT: fp32, ragged C, R = out stride ----------------
__global__ void binT_k(const float* __restrict__ in, uint8_t* __restrict__ out,
                       int R, int C)
{
    __shared__ float t[32][33];
    const int c0 = blockIdx.x * 32, r0 = blockIdx.y * 32;
    const int tx = threadIdx.x, ty = threadIdx.y;  // 32 x 8
#pragma unroll
    for (int i = 0; i < 4; i++) {
        int r = r0 + ty + i * 8, c = c0 + tx;
        t[ty + i * 8][tx] = (c < C) ? in[(size_t)r * C + c] : 0.f;
    }
    __syncthreads();
#pragma unroll
    for (int i = 0; i < 4; i++) {
        int oc = c0 + ty + i * 8;
        if (oc < C)
            out[(size_t)oc * R + r0 + tx] = (t[tx][ty + i * 8] > 0.f) ? FP8_ONE : 0;
    }
}

// ---------------- forward GEMM: single fp16 MMA, warp grid 4x2 ---------------
// MODE 1: relu, fp16 out (Ch). MODE 2: fp32 out (Cf).
#define STAGES 3
#define FWD_STG 16384
#define FWD_SMEM (FWD_STG * STAGES)
template <int MODE>
__global__ void __launch_bounds__(256)
gemm_fwd(const __half* __restrict__ A, const __half* __restrict__ B,
         const float* __restrict__ bias, float* __restrict__ Cf,
         __half* __restrict__ Ch, int M, int N, int K)
{
    extern __shared__ char smem[];
    const uint32_t sb = su32(smem);

    const int tid = threadIdx.x;
    const int lane = tid & 31, wid = tid >> 5;
    const int warp_m = wid & 3, warp_n = wid >> 2;     // 4 x 2 warps, 32x64 each
    const int m0 = blockIdx.y * 128, n0 = blockIdx.x * 128;

    float acc[2][8][4];
#pragma unroll
    for (int mi = 0; mi < 2; mi++)
#pragma unroll
        for (int ni = 0; ni < 8; ni++)
#pragma unroll
            for (int e = 0; e < 4; e++) acc[mi][ni][e] = 0.f;

    const int T = K >> 5;

    auto issue = [&](int t) {
        const uint32_t s = sb + (t % STAGES) * FWD_STG;
        const int k0 = t * 32;
#pragma unroll
        for (int j = 0; j < 2; j++) {
            const int cid = j * 256 + tid;
            const int row = cid >> 2, ch = cid & 3;
            const uint32_t soff = tadr(row, ch);
            cpa(s + soff, A + (size_t)(m0 + row) * K + k0 + ch * 8, 16);
            const int brow = n0 + row;
            const int ok = brow < N;
            cpa(s + 8192 + soff, B + (size_t)(ok ? brow : 0) * K + k0 + ch * 8, ok ? 16 : 0);
        }
        CP_COMMIT();
    };

    issue(0);
    issue(1);

    for (int t = 0; t < T; t++) {
        if (t == T - 1) CP_WAIT0(); else CP_WAIT1();
        __syncthreads();
        if (t + 2 < T) issue(t + 2);

        const uint32_t s = sb + (t % STAGES) * FWD_STG;
        const uint32_t sA = s, sB = s + 8192;

#pragma unroll
        for (int ks = 0; ks < 2; ks++) {
            uint32_t ah[2][4];
#pragma unroll
            for (int mi = 0; mi < 2; mi++) {
                const int row = warp_m * 32 + mi * 16 + (lane & 15);
                const int ch = ks * 2 + (lane >> 4);
                ldsm4(ah[mi], sA + tadr(row, ch));
            }
#pragma unroll
            for (int np = 0; np < 4; np++) {
                uint32_t bq[4];
                const int row = warp_n * 64 + (np * 2 + (lane >> 4)) * 8 + (lane & 7);
                const int ch = ks * 2 + ((lane >> 3) & 1);
                ldsm4(bq, sB + tadr(row, ch));
#pragma unroll
                for (int mi = 0; mi < 2; mi++) {
                    mma_f16(acc[mi][np * 2], ah[mi], bq);
                    mma_f16(acc[mi][np * 2 + 1], ah[mi], bq + 2);
                }
            }
        }
    }

#pragma unroll
    for (int mi = 0; mi < 2; mi++) {
        const int r0 = m0 + warp_m * 32 + mi * 16 + (lane >> 2);
#pragma unroll
        for (int ni = 0; ni < 8; ni++) {
            const int col = n0 + warp_n * 64 + ni * 8 + (lane & 3) * 2;
            if (col < N) {
                const float b0 = __ldg(bias + col), b1 = __ldg(bias + col + 1);
                float2 v0 = make_float2(acc[mi][ni][0] + b0, acc[mi][ni][1] + b1);
                float2 v1 = make_float2(acc[mi][ni][2] + b0, acc[mi][ni][3] + b1);
                if (MODE == 1) {
                    v0.x = fmaxf(v0.x, 0.f); v0.y = fmaxf(v0.y, 0.f);
                    v1.x = fmaxf(v1.x, 0.f); v1.y = fmaxf(v1.y, 0.f);
                    *(uint32_t*)(Ch + (size_t)r0 * N + col) =
                        pkh(__float2half(v0.x), __float2half(v0.y));
                    *(uint32_t*)(Ch + (size_t)(r0 + 8) * N + col) =
                        pkh(__float2half(v1.x), __float2half(v1.y));
                } else {
                    *(float2*)(Cf + (size_t)r0 * N + col) = v0;
                    *(float2*)(Cf + (size_t)(r0 + 8) * N + col) = v1;
                }
            }
        }
    }
}

// ---------------- coact GEMM: fp8 e4m3 0/1, exact; K-chunk 64B ---------------
#define CO_STG 16384
#define CO_SMEM (CO_STG * STAGES)
template <bool ACCUM>
__global__ void __launch_bounds__(256)
gemm_co(const uint8_t* __restrict__ A, const uint8_t* __restrict__ B,
        float* __restrict__ C, int M, int N, int ldk, int K)
{
    extern __shared__ char smem[];
    const uint32_t sb = su32(smem);

    const int tid = threadIdx.x;
    const int lane = tid & 31, wid = tid >> 5;
    const int warp_m = wid & 1, warp_n = wid >> 1;     // 2 x 4, warp tile 64x32
    const int m0 = blockIdx.y * 128, n0 = blockIdx.x * 128;

    float acc[4][4][4];
#pragma unroll
    for (int mi = 0; mi < 4; mi++)
#pragma unroll
        for (int ni = 0; ni < 4; ni++)
#pragma unroll
            for (int e = 0; e < 4; e++) acc[mi][ni][e] = 0.f;

    const int T = K >> 6;

    auto issue = [&](int t) {
        const uint32_t s = sb + (t % STAGES) * CO_STG;
        const int k0 = t * 64;
#pragma unroll
        for (int j = 0; j < 2; j++) {
            const int cid = j * 256 + tid;
            const int row = cid >> 2, ch = cid & 3;
            const uint32_t soff = tadr(row, ch);
            cpa(s + soff, A + (size_t)(m0 + row) * ldk + k0 + ch * 16, 16);
            const int brow = n0 + row;
            const int ok = brow < N;
            cpa(s + 8192 + soff, B + (size_t)(ok ? brow : 0) * ldk + k0 + ch * 16, ok ? 16 : 0);
        }
        CP_COMMIT();
    };

    issue(0);
    issue(1);

    for (int t = 0; t < T; t++) {
        if (t == T - 1) CP_WAIT0(); else CP_WAIT1();
        __syncthreads();
        if (t + 2 < T) issue(t + 2);

        const uint32_t s = sb + (t % STAGES) * CO_STG;
        const uint32_t sA = s, sB = s + 8192;

        uint32_t bq[4][4];
#pragma unroll
        for (int ni = 0; ni < 4; ni++) {
            const int row = warp_n * 32 + ni * 8 + (lane & 7);
            const int ch = lane >> 3;
            ldsm4(bq[ni], sB + tadr(row, ch));
        }
#pragma unroll
        for (int ks = 0; ks < 2; ks++) {
            uint32_t a[4][4];
#pragma unroll
            for (int mi = 0; mi < 4; mi++) {
                const int row = warp_m * 64 + mi * 16 + (lane & 15);
                const int ch = ks * 2 + (lane >> 4);
                ldsm4(a[mi], sA + tadr(row, ch));
            }
#pragma unroll
            for (int mi = 0; mi < 4; mi++)
#pragma unroll
                for (int ni = 0; ni < 4; ni++)
                    mma_e4m3(acc[mi][ni], a[mi], &bq[ni][2 * ks]);
        }
    }

#pragma unroll
    for (int mi = 0; mi < 4; mi++) {
        const int r0 = m0 + warp_m * 64 + mi * 16 + (lane >> 2);
#pragma unroll
        for (int ni = 0; ni < 4; ni++) {
            const int col = n0 + warp_n * 32 + ni * 8 + (lane & 3) * 2;
            if (col < N) {
                float2 v0 = make_float2(acc[mi][ni][0], acc[mi][ni][1]);
                float2 v1 = make_float2(acc[mi][ni][2], acc[mi][ni][3]);
                if (ACCUM) {
                    float2 o0 = *(float2*)(C + (size_t)r0 * N + col);
                    float2 o1 = *(float2*)(C + (size_t)(r0 + 8) * N + col);
                    v0.x += o0.x; v0.y += o0.y; v1.x += o1.x; v1.y += o1.y;
                }
                *(float2*)(C + (size_t)r0 * N + col) = v0;
                *(float2*)(C + (size_t)(r0 + 8) * N + col) = v1;
            }
        }
    }
}

// ---------------- launch -----------------------------------------------------
extern "C" void kernel_launch(void* const* d_in, const int* in_sizes, int n_in,
                              void* d_out, int out_size)
{
    const float* x  = (const float*)d_in[0];
    const float* W1 = (const float*)d_in[1];
    const float* b1 = (const float*)d_in[2];
    const float* W2 = (const float*)d_in[3];
    const float* b2 = (const float*)d_in[4];
    const float* W3 = (const float*)d_in[5];
    const float* b3 = (const float*)d_in[6];

    float* out    = (float*)d_out;
    float* logits = out;
    float* coact0 = logits + (size_t)BATCH * N_CLS;
    float* coact1 = coact0 + (size_t)D_IN * H1;
    float* coact2 = coact1 + (size_t)H1 * H2;

    __half *xh, *a1h, *a2h, *w1h, *w2h, *w3h;
    uint8_t *xbT, *a1bT, *a2bT, *lbT;
    cudaGetSymbolAddress((void**)&xh, g_xh);
    cudaGetSymbolAddress((void**)&a1h, g_a1h);
    cudaGetSymbolAddress((void**)&a2h, g_a2h);
    cudaGetSymbolAddress((void**)&w1h, g_w1h);
    cudaGetSymbolAddress((void**)&w2h, g_w2h);
    cudaGetSymbolAddress((void**)&w3h, g_w3h);
    cudaGetSymbolAddress((void**)&xbT, g_xbT);   cudaGetSymbolAddress((void**)&a1bT, g_a1bT);
    cudaGetSymbolAddress((void**)&a2bT, g_a2bT); cudaGetSymbolAddress((void**)&lbT, g_lbT);

    static bool s_init = false;
    static cudaStream_t s_side;
    static cudaEvent_t evFork, evW23, evPrep1, evPrep2, evC0, evC1, evL3a, evC2a;
    if (!s_init) {
        cudaStreamCreateWithFlags(&s_side, cudaStreamNonBlocking);
        cudaEventCreateWithFlags(&evFork, cudaEventDisableTiming);
        cudaEventCreateWithFlags(&evW23, cudaEventDisableTiming);
        cudaEventCreateWithFlags(&evPrep1, cudaEventDisableTiming);
        cudaEventCreateWithFlags(&evPrep2, cudaEventDisableTiming);
        cudaEventCreateWithFlags(&evC0, cudaEventDisableTiming);
        cudaEventCreateWithFlags(&evC1, cudaEventDisableTiming);
        cudaEventCreateWithFlags(&evL3a, cudaEventDisableTiming);
        cudaEventCreateWithFlags(&evC2a, cudaEventDisableTiming);
        cudaFuncSetAttribute(gemm_fwd<1>, cudaFuncAttributeMaxDynamicSharedMemorySize, FWD_SMEM);
        cudaFuncSetAttribute(gemm_fwd<2>, cudaFuncAttributeMaxDynamicSharedMemorySize, FWD_SMEM);
        cudaFuncSetAttribute(gemm_co<false>, cudaFuncAttributeMaxDynamicSharedMemorySize, CO_SMEM);
        cudaFuncSetAttribute(gemm_co<true>, cudaFuncAttributeMaxDynamicSharedMemorySize, CO_SMEM);
        s_init = true;
    }

    const dim3 blk(256);
    const dim3 tb(32, 8);

    // capture-legal fork
    cudaEventRecord(evFork, 0);
    cudaStreamWaitEvent(s_side, evFork, 0);

    // main: prepack for fwd1
    post_k<<<dim3(D_IN / 32, BATCH / 32), tb>>>(x, xh, xbT, BATCH, D_IN);
    w16_k<<<1024, 256>>>(W1, w1h, (size_t)H1 * D_IN / 4);

    // side: W2/W3 fp16 overlap fwd1
    w16_k<<<1024, 256, 0, s_side>>>(W2, w2h, (size_t)H2 * H1 / 4);
    w16_k<<<1024, 256, 0, s_side>>>(W3, w3h, (size_t)N_CLS * H2 / 4);
    cudaEventRecord(evW23, s_side);

    // fwd1: writes a1h fp16 directly; binT from fp16
    gemm_fwd<1><<<dim3(H1 / 128, BATCH / 128), blk, FWD_SMEM>>>(
        xh, w1h, b1, nullptr, a1h, BATCH, H1, D_IN);
    binT16_k<<<dim3(H1 / 32, BATCH / 32), tb>>>(a1h, a1bT, BATCH, H1);
    cudaEventRecord(evPrep1, 0);

    // side: coact0 overlaps fwd2
    cudaStreamWaitEvent(s_side, evPrep1, 0);
    gemm_co<false><<<dim3(H1 / 128, D_IN / 128), blk, CO_SMEM, s_side>>>(
        xbT, a1bT, coact0, D_IN, H1, BATCH, BATCH);
    cudaEventRecord(evC0, s_side);

    // fwd2: writes a2h fp16 directly
    cudaStreamWaitEvent(0, evW23, 0);
    gemm_fwd<1><<<dim3(H2 / 128, BATCH / 128), blk, FWD_SMEM>>>(
        a1h, w2h, b2, nullptr, a2h, BATCH, H2, H1);
    binT16_k<<<dim3(H2 / 32, BATCH / 32), tb>>>(a2h, a2bT, BATCH, H2);
    cudaEventRecord(evPrep2, 0);

    // side: coact1 overlaps fwd3
    cudaStreamWaitEvent(s_side, evPrep2, 0);
    gemm_co<false><<<dim3(H2 / 128, H1 / 128), blk, CO_SMEM, s_side>>>(
        a1bT, a2bT, coact1, H1, H2, BATCH, BATCH);
    cudaEventRecord(evC1, s_side);

    // fwd3a: logits rows [0, HALF_B) (fp32 output)
    gemm_fwd<2><<<dim3((N_CLS + 127) / 128, HALF_B / 128), blk, FWD_SMEM>>>(
        a2h, w3h, b3, logits, nullptr, HALF_B, N_CLS, H2);
    cudaEventRecord(evL3a, 0);

    // side: binT(logits a) + coact2a overlap fwd3b
    cudaStreamWaitEvent(s_side, evL3a, 0);
    binT_k<<<dim3((N_CLS + 31) / 32, HALF_B / 32), tb, 0, s_side>>>(
        logits, lbT, BATCH, N_CLS);
    gemm_co<false><<<dim3((N_CLS + 127) / 128, H2 / 128), blk, CO_SMEM, s_side>>>(
        a2bT, lbT, coact2, H2, N_CLS, BATCH, HALF_B);
    cudaEventRecord(evC2a, s_side);

    // fwd3b
    gemm_fwd<2><<<dim3((N_CLS + 127) / 128, HALF_B / 128), blk, FWD_SMEM>>>(
        a2h + (size_t)HALF_B * H2, w3h, b3,
        logits + (size_t)HALF_B * N_CLS, nullptr, HALF_B, N_CLS, H2);
    binT_k<<<dim3((N_CLS + 31) / 32, HALF_B / 32), tb>>>(
        logits + (size_t)HALF_B * N_CLS, lbT + HALF_B, BATCH, N_CLS);

    // coact2b: accumulate second K-half
    cudaStreamWaitEvent(0, evC2a, 0);
    gemm_co<true><<<dim3((N_CLS + 127) / 128, H2 / 128), blk, CO_SMEM>>>(
        a2bT + HALF_B, lbT + HALF_B, coact2, H2, N_CLS, BATCH, HALF_B);

    // join side stream
    cudaStreamWaitEvent(0, evC0, 0);
    cudaStreamWaitEvent(0, evC1, 0);
}